// round 1
// baseline (speedup 1.0000x reference)
#include <cuda_runtime.h>
#include <math.h>

// Problem constants (R=1024, S=128, J=24, H=64, multires=6)
constexpr int NPTS = 1024 * 128;   // 131072 points
constexpr int NJ   = 24;           // joints
constexpr int NH   = 64;           // hidden dim
constexpr int NI   = 39;           // per-joint encoded dims: 3*(1+2*6)

// relu(h) stored row-major [NPTS, NJ]; kernel 2 reads the faithful
// view(J,-1).T scramble as a linear index j*NPTS + m into this buffer.
__device__ float g_h[(size_t)NPTS * NJ];

// ---------------------------------------------------------------------------
// Kernel 1: per-point fused  transform -> freq-encode -> MLP(936->64->24)
// One thread = one point. w0 tiled per-joint (39x64 floats = 10KB) in SMEM,
// broadcast float4 reads. 64 fp32 accumulators in registers.
// ---------------------------------------------------------------------------

#define ROWP(wr, e)                                                         \
    {                                                                       \
        _Pragma("unroll") for (int k = 0; k < 16; ++k) {                    \
            float4 w = (wr)[k];                                             \
            acc[k].x = fmaf((e), w.x, acc[k].x);                            \
            acc[k].y = fmaf((e), w.y, acc[k].y);                            \
            acc[k].z = fmaf((e), w.z, acc[k].z);                            \
            acc[k].w = fmaf((e), w.w, acc[k].w);                            \
        }                                                                   \
    }

__global__ __launch_bounds__(128, 3)
void weights_kernel(const float* __restrict__ xyz,
                    const float* __restrict__ transforms,
                    const float* __restrict__ w0,
                    const float* __restrict__ w1)
{
    __shared__ float4 sw0[NI * 16];   // one joint's w0 slice: 39 x 64 floats
    __shared__ float  sw1[NH * NJ];   // full w1: 64 x 24
    __shared__ float  str[NJ * 16];   // all transforms

    const int tid = threadIdx.x;
    const int n   = blockIdx.x * 128 + tid;

    for (int i = tid; i < (NH * NJ) / 4; i += 128)
        ((float4*)sw1)[i] = ((const float4*)w1)[i];
    for (int i = tid; i < NJ * 16; i += 128)
        str[i] = transforms[i];

    const float x = xyz[3 * n + 0];
    const float y = xyz[3 * n + 1];
    const float z = xyz[3 * n + 2];

    float4 acc[16];
#pragma unroll
    for (int k = 0; k < 16; ++k) acc[k] = make_float4(0.f, 0.f, 0.f, 0.f);

    for (int j = 0; j < NJ; ++j) {
        __syncthreads();   // previous tile fully consumed (also orders sw1/str on j==0)
        {
            const float4* src = ((const float4*)w0) + (size_t)j * (NI * 16);
            for (int i = tid; i < NI * 16; i += 128) sw0[i] = src[i];
        }
        __syncthreads();

        const float* T = &str[j * 16];
        float lx = fmaf(T[0], x, fmaf(T[1], y, fmaf(T[2],  z, T[3])));
        float ly = fmaf(T[4], x, fmaf(T[5], y, fmaf(T[6],  z, T[7])));
        float lz = fmaf(T[8], x, fmaf(T[9], y, fmaf(T[10], z, T[11])));
        const float INV = 2.0f / 3.0f;   // normalize_coord: (v+1.5)*(2/3)-1
        lx = (lx + 1.5f) * INV - 1.0f;
        ly = (ly + 1.5f) * INV - 1.0f;
        lz = (lz + 1.5f) * INV - 1.0f;

        // rows 0..2: raw coords
        ROWP(&sw0[0 * 16], lx)
        ROWP(&sw0[1 * 16], ly)
        ROWP(&sw0[2 * 16], lz)

        // rows 3..38: for f: [sin(2^f x), sin y, sin z, cos x, cos y, cos z]
        float fx = lx, fy = ly, fz = lz;
#pragma unroll 1
        for (int f = 0; f < 6; ++f) {
            float sx, cx, sy, cy, sz, cz;
            __sincosf(fx, &sx, &cx);
            __sincosf(fy, &sy, &cy);
            __sincosf(fz, &sz, &cz);
            const float4* wr = &sw0[(3 + 6 * f) * 16];
            ROWP(wr + 0 * 16, sx)
            ROWP(wr + 1 * 16, sy)
            ROWP(wr + 2 * 16, sz)
            ROWP(wr + 3 * 16, cx)
            ROWP(wr + 4 * 16, cy)
            ROWP(wr + 5 * 16, cz)
            fx += fx; fy += fy; fz += fz;   // exact power-of-two freq step
        }
    }

    // Layer 2: h = relu(acc) @ w1, then sigma = relu(h), stored row-major [N, NJ]
    float ra[NH];
    const float* af = (const float*)acc;
#pragma unroll
    for (int k = 0; k < NH; ++k) ra[k] = fmaxf(af[k], 0.f);

    float* gout = &g_h[(size_t)n * NJ];
#pragma unroll 1
    for (int jj = 0; jj < NJ; ++jj) {
        float s = 0.f;
#pragma unroll
        for (int k = 0; k < NH; ++k) s = fmaf(ra[k], sw1[k * NJ + jj], s);
        gout[jj] = fmaxf(s, 0.f);
    }
}

// ---------------------------------------------------------------------------
// Kernel 2: scrambled-weight readback + normalized transform blend.
// weights[m, j] = relu(h).flat[j*NPTS + m]  (the faithful view(J,-1).T)
// out1 = sum_j wn * (T_j @ [p,1])[:3]
// out2 = sum_j wn * (T_j @ [p - v, 1])[:3]
// xyz_warped = out1 ; vd_warped = out1 - out2  (exactly as reference)
// ---------------------------------------------------------------------------
__global__ __launch_bounds__(256)
void warp_kernel(const float* __restrict__ xyz,
                 const float* __restrict__ vdir,
                 const float* __restrict__ transforms,
                 float* __restrict__ out)
{
    __shared__ float str[NJ * 16];
    const int tid = threadIdx.x;
    const int m   = blockIdx.x * 256 + tid;
    for (int i = tid; i < NJ * 16; i += 256) str[i] = transforms[i];
    __syncthreads();

    float w[NJ];
    float s = 0.f;
#pragma unroll
    for (int j = 0; j < NJ; ++j) {
        w[j] = g_h[(size_t)j * NPTS + m];   // coalesced: fixed j, consecutive m
        s += w[j];
    }
    const float inv = 1.0f / (s + 1e-6f);

    const float x  = xyz[3 * m + 0], y  = xyz[3 * m + 1], z  = xyz[3 * m + 2];
    const float vx = vdir[3 * m + 0], vy = vdir[3 * m + 1], vz = vdir[3 * m + 2];
    const float x2 = x - vx, y2 = y - vy, z2 = z - vz;

    float a1x = 0.f, a1y = 0.f, a1z = 0.f;
    float a2x = 0.f, a2y = 0.f, a2z = 0.f;
#pragma unroll
    for (int j = 0; j < NJ; ++j) {
        const float wn = w[j] * inv;
        const float* T = &str[j * 16];
        a1x = fmaf(wn, fmaf(T[0], x,  fmaf(T[1], y,  fmaf(T[2],  z,  T[3]))),  a1x);
        a1y = fmaf(wn, fmaf(T[4], x,  fmaf(T[5], y,  fmaf(T[6],  z,  T[7]))),  a1y);
        a1z = fmaf(wn, fmaf(T[8], x,  fmaf(T[9], y,  fmaf(T[10], z,  T[11]))), a1z);
        a2x = fmaf(wn, fmaf(T[0], x2, fmaf(T[1], y2, fmaf(T[2],  z2, T[3]))),  a2x);
        a2y = fmaf(wn, fmaf(T[4], x2, fmaf(T[5], y2, fmaf(T[6],  z2, T[7]))),  a2y);
        a2z = fmaf(wn, fmaf(T[8], x2, fmaf(T[9], y2, fmaf(T[10], z2, T[11]))), a2z);
    }

    out[3 * m + 0] = a1x;
    out[3 * m + 1] = a1y;
    out[3 * m + 2] = a1z;
    float* o2 = out + (size_t)3 * NPTS;
    o2[3 * m + 0] = a1x - a2x;
    o2[3 * m + 1] = a1y - a2y;
    o2[3 * m + 2] = a1z - a2z;
}

// ---------------------------------------------------------------------------
// Inputs (metadata order): xyz_sampled, viewdirs, transforms, ray_valid, w0, w1
// ray_valid is all-true and unused by the reference.
// Output: [xyz_warped (N*3) | vd_warped (N*3)] float32.
// ---------------------------------------------------------------------------
extern "C" void kernel_launch(void* const* d_in, const int* in_sizes, int n_in,
                              void* d_out, int out_size)
{
    const float* xyz = (const float*)d_in[0];
    const float* vd  = (const float*)d_in[1];
    const float* tr  = (const float*)d_in[2];
    const float* w0  = (const float*)d_in[4];
    const float* w1  = (const float*)d_in[5];
    float* out = (float*)d_out;

    weights_kernel<<<NPTS / 128, 128>>>(xyz, tr, w0, w1);
    warp_kernel<<<NPTS / 256, 256>>>(xyz, vd, tr, out);
}

// round 2
// speedup vs baseline: 1.2032x; 1.2032x over previous
#include <cuda_runtime.h>
#include <math.h>

// Problem constants (R=1024, S=128, J=24, H=64, multires=6)
constexpr int NPTS = 1024 * 128;   // 131072 points
constexpr int NJ   = 24;           // joints
constexpr int NH   = 64;           // hidden dim
constexpr int NI   = 39;           // per-joint encoded dims: 3*(1+2*6)

// relu(h) stored row-major [NPTS, NJ]; kernel 2 reads the faithful
// view(J,-1).T scramble as a linear index j*NPTS + m into this buffer.
__device__ float g_h[(size_t)NPTS * NJ];

// ---------------------------------------------------------------------------
// Packed f32x2 helpers (Blackwell FFMA2 — only reachable via PTX fma.rn.f32x2)
// ---------------------------------------------------------------------------
__device__ __forceinline__ unsigned long long pack2(float e) {
    unsigned long long r;
    asm("mov.b64 %0, {%1, %1};" : "=l"(r) : "f"(e));
    return r;
}
__device__ __forceinline__ void ffma2(unsigned long long& acc,
                                      unsigned long long a,
                                      unsigned long long b) {
    asm("fma.rn.f32x2 %0, %1, %2, %0;" : "+l"(acc) : "l"(a), "l"(b));
}
__device__ __forceinline__ float2 unpack2(unsigned long long v) {
    float2 r;
    asm("mov.b64 {%0, %1}, %2;" : "=f"(r.x), "=f"(r.y) : "l"(v));
    return r;
}

// One input row: 16 ulonglong2 loads (== float4 weight quads), 32 FFMA2.
// acc2[2k]   accumulates hidden cols (4k, 4k+1)
// acc2[2k+1] accumulates hidden cols (4k+2, 4k+3)
#define ROWP2(wr, e2)                                                       \
    {                                                                       \
        _Pragma("unroll") for (int k = 0; k < 16; ++k) {                    \
            ulonglong2 w = (wr)[k];                                         \
            ffma2(acc2[2 * k + 0], (e2), w.x);                              \
            ffma2(acc2[2 * k + 1], (e2), w.y);                              \
        }                                                                   \
    }

// ---------------------------------------------------------------------------
// Kernel 1: per-point fused  transform -> freq-encode -> MLP(936->64->24)
// One thread = one point. w0 tiled per-joint (39x64 floats = 10KB) in SMEM,
// broadcast 16B reads. 64 fp32 accumulators held as 32 packed f32x2 regs.
// ---------------------------------------------------------------------------
__global__ __launch_bounds__(128, 3)
void weights_kernel(const float* __restrict__ xyz,
                    const float* __restrict__ transforms,
                    const float* __restrict__ w0,
                    const float* __restrict__ w1)
{
    __shared__ float4 sw0[NI * 16];   // one joint's w0 slice: 39 x 64 floats
    __shared__ float  sw1[NH * NJ];   // full w1: 64 x 24
    __shared__ float  str[NJ * 16];   // all transforms

    const int tid = threadIdx.x;
    const int n   = blockIdx.x * 128 + tid;

    for (int i = tid; i < (NH * NJ) / 4; i += 128)
        ((float4*)sw1)[i] = ((const float4*)w1)[i];
    for (int i = tid; i < NJ * 16; i += 128)
        str[i] = transforms[i];

    const float x = xyz[3 * n + 0];
    const float y = xyz[3 * n + 1];
    const float z = xyz[3 * n + 2];

    unsigned long long acc2[32];
#pragma unroll
    for (int k = 0; k < 32; ++k) acc2[k] = 0ULL;   // (+0.f, +0.f)

    const ulonglong2* sw0u = (const ulonglong2*)sw0;

    for (int j = 0; j < NJ; ++j) {
        __syncthreads();   // previous tile fully consumed (also orders sw1/str on j==0)
        {
            const float4* src = ((const float4*)w0) + (size_t)j * (NI * 16);
            for (int i = tid; i < NI * 16; i += 128) sw0[i] = src[i];
        }
        __syncthreads();

        const float* T = &str[j * 16];
        float lx = fmaf(T[0], x, fmaf(T[1], y, fmaf(T[2],  z, T[3])));
        float ly = fmaf(T[4], x, fmaf(T[5], y, fmaf(T[6],  z, T[7])));
        float lz = fmaf(T[8], x, fmaf(T[9], y, fmaf(T[10], z, T[11])));
        const float INV = 2.0f / 3.0f;   // normalize_coord: (v+1.5)*(2/3)-1
        lx = (lx + 1.5f) * INV - 1.0f;
        ly = (ly + 1.5f) * INV - 1.0f;
        lz = (lz + 1.5f) * INV - 1.0f;

        // rows 0..2: raw coords
        ROWP2(&sw0u[0 * 16], pack2(lx))
        ROWP2(&sw0u[1 * 16], pack2(ly))
        ROWP2(&sw0u[2 * 16], pack2(lz))

        // rows 3..38: for f: [sin(2^f x), sin y, sin z, cos x, cos y, cos z]
        float fx = lx, fy = ly, fz = lz;
#pragma unroll 1
        for (int f = 0; f < 6; ++f) {
            float sx, cx, sy, cy, sz, cz;
            __sincosf(fx, &sx, &cx);
            __sincosf(fy, &sy, &cy);
            __sincosf(fz, &sz, &cz);
            const ulonglong2* wr = &sw0u[(3 + 6 * f) * 16];
            ROWP2(wr + 0 * 16, pack2(sx))
            ROWP2(wr + 1 * 16, pack2(sy))
            ROWP2(wr + 2 * 16, pack2(sz))
            ROWP2(wr + 3 * 16, pack2(cx))
            ROWP2(wr + 4 * 16, pack2(cy))
            ROWP2(wr + 5 * 16, pack2(cz))
            fx += fx; fy += fy; fz += fz;   // exact power-of-two freq step
        }
    }

    // Layer 2: h = relu(acc) @ w1, then sigma = relu(h), stored row-major [N, NJ]
    float ra[NH];
#pragma unroll
    for (int k = 0; k < 32; ++k) {
        float2 v = unpack2(acc2[k]);
        ra[2 * k + 0] = fmaxf(v.x, 0.f);
        ra[2 * k + 1] = fmaxf(v.y, 0.f);
    }

    float* gout = &g_h[(size_t)n * NJ];
#pragma unroll 1
    for (int jj = 0; jj < NJ; ++jj) {
        float s = 0.f;
#pragma unroll
        for (int k = 0; k < NH; ++k) s = fmaf(ra[k], sw1[k * NJ + jj], s);
        gout[jj] = fmaxf(s, 0.f);
    }
}

// ---------------------------------------------------------------------------
// Kernel 2: scrambled-weight readback + normalized transform blend.
// weights[m, j] = relu(h).flat[j*NPTS + m]  (the faithful view(J,-1).T)
// out1 = sum_j wn * (T_j @ [p,1])[:3]
// out2 = sum_j wn * (T_j @ [p - v, 1])[:3]
// xyz_warped = out1 ; vd_warped = out1 - out2  (exactly as reference)
// ---------------------------------------------------------------------------
__global__ __launch_bounds__(256)
void warp_kernel(const float* __restrict__ xyz,
                 const float* __restrict__ vdir,
                 const float* __restrict__ transforms,
                 float* __restrict__ out)
{
    __shared__ float str[NJ * 16];
    const int tid = threadIdx.x;
    const int m   = blockIdx.x * 256 + tid;
    for (int i = tid; i < NJ * 16; i += 256) str[i] = transforms[i];
    __syncthreads();

    float w[NJ];
    float s = 0.f;
#pragma unroll
    for (int j = 0; j < NJ; ++j) {
        w[j] = g_h[(size_t)j * NPTS + m];   // coalesced: fixed j, consecutive m
        s += w[j];
    }
    const float inv = 1.0f / (s + 1e-6f);

    const float x  = xyz[3 * m + 0], y  = xyz[3 * m + 1], z  = xyz[3 * m + 2];
    const float vx = vdir[3 * m + 0], vy = vdir[3 * m + 1], vz = vdir[3 * m + 2];
    const float x2 = x - vx, y2 = y - vy, z2 = z - vz;

    float a1x = 0.f, a1y = 0.f, a1z = 0.f;
    float a2x = 0.f, a2y = 0.f, a2z = 0.f;
#pragma unroll
    for (int j = 0; j < NJ; ++j) {
        const float wn = w[j] * inv;
        const float* T = &str[j * 16];
        a1x = fmaf(wn, fmaf(T[0], x,  fmaf(T[1], y,  fmaf(T[2],  z,  T[3]))),  a1x);
        a1y = fmaf(wn, fmaf(T[4], x,  fmaf(T[5], y,  fmaf(T[6],  z,  T[7]))),  a1y);
        a1z = fmaf(wn, fmaf(T[8], x,  fmaf(T[9], y,  fmaf(T[10], z,  T[11]))), a1z);
        a2x = fmaf(wn, fmaf(T[0], x2, fmaf(T[1], y2, fmaf(T[2],  z2, T[3]))),  a2x);
        a2y = fmaf(wn, fmaf(T[4], x2, fmaf(T[5], y2, fmaf(T[6],  z2, T[7]))),  a2y);
        a2z = fmaf(wn, fmaf(T[8], x2, fmaf(T[9], y2, fmaf(T[10], z2, T[11]))), a2z);
    }

    out[3 * m + 0] = a1x;
    out[3 * m + 1] = a1y;
    out[3 * m + 2] = a1z;
    float* o2 = out + (size_t)3 * NPTS;
    o2[3 * m + 0] = a1x - a2x;
    o2[3 * m + 1] = a1y - a2y;
    o2[3 * m + 2] = a1z - a2z;
}

// ---------------------------------------------------------------------------
// Inputs (metadata order): xyz_sampled, viewdirs, transforms, ray_valid, w0, w1
// ray_valid is all-true and unused by the reference.
// Output: [xyz_warped (N*3) | vd_warped (N*3)] float32.
// ---------------------------------------------------------------------------
extern "C" void kernel_launch(void* const* d_in, const int* in_sizes, int n_in,
                              void* d_out, int out_size)
{
    const float* xyz = (const float*)d_in[0];
    const float* vd  = (const float*)d_in[1];
    const float* tr  = (const float*)d_in[2];
    const float* w0  = (const float*)d_in[4];
    const float* w1  = (const float*)d_in[5];
    float* out = (float*)d_out;

    weights_kernel<<<NPTS / 128, 128>>>(xyz, tr, w0, w1);
    warp_kernel<<<NPTS / 256, 256>>>(xyz, vd, tr, out);
}

// round 4
// speedup vs baseline: 2.1471x; 1.7845x over previous
#include <cuda_runtime.h>
#include <cuda_bf16.h>
#include <cstdint>
#include <math.h>

// Problem constants (R=1024, S=128, J=24, H=64, multires=6)
constexpr int NPTS = 1024 * 128;
constexpr int NJ   = 24;
constexpr int NH   = 64;
constexpr int NI   = 39;

// ---- SMEM layout (static, 44032 B, mainloop/epilogue union) ----
// mainloop:  AH[128x112B] AL[128x112B] BH[48x144B] BL[48x144B]
// epilogue:  H[128x65 f32] W1[64x24 f32]
// always:    TR[24x16 f32]
constexpr int SM_AH = 0;
constexpr int SM_AL = SM_AH + 128 * 112;   // 14336
constexpr int SM_BH = SM_AL + 128 * 112;   // 28672
constexpr int SM_BL = SM_BH + 48 * 144;    // 35584
constexpr int SM_H  = 0;                   // 128*65*4 = 33280
constexpr int SM_W1 = 33280;               // 6144
constexpr int SM_TR = SM_BL + 48 * 144;    // 42496
constexpr int SM_SZ = SM_TR + NJ * 16 * 4; // 44032

// relu(h) row-major [NPTS, NJ]; warp_kernel reads the faithful view(J,-1).T
// scramble as linear index j*NPTS + m.
__device__ float g_h[(size_t)NPTS * NJ];
// Pre-split B images: per joint [48 k][72 n-stride] bf16 (144B rows, byte-exact
// copy of the SMEM tile). B[k][n] = w0[j*39+k][n], zero for k>=39.
__device__ __align__(16) unsigned short g_Bh[NJ * 48 * 72];
__device__ __align__(16) unsigned short g_Bl[NJ * 48 * 72];

// ---------------- helpers ----------------
__device__ __forceinline__ uint32_t smem_u32(const void* p) {
    uint32_t a;
    asm("{ .reg .u64 t; cvta.to.shared.u64 t, %1; cvt.u32.u64 %0, t; }" : "=r"(a) : "l"(p));
    return a;
}
__device__ __forceinline__ void ldsm4(uint32_t* r, uint32_t addr) {
    asm volatile("ldmatrix.sync.aligned.m8n8.x4.shared.b16 {%0,%1,%2,%3}, [%4];"
                 : "=r"(r[0]), "=r"(r[1]), "=r"(r[2]), "=r"(r[3]) : "r"(addr));
}
__device__ __forceinline__ void ldsm4t(uint32_t* r, uint32_t addr) {
    asm volatile("ldmatrix.sync.aligned.m8n8.x4.trans.shared.b16 {%0,%1,%2,%3}, [%4];"
                 : "=r"(r[0]), "=r"(r[1]), "=r"(r[2]), "=r"(r[3]) : "r"(addr));
}
__device__ __forceinline__ void mma16816(float* d, const uint32_t* a,
                                         uint32_t b0, uint32_t b1) {
    asm volatile(
        "mma.sync.aligned.m16n8k16.row.col.f32.bf16.bf16.f32 "
        "{%0,%1,%2,%3}, {%4,%5,%6,%7}, {%8,%9}, {%0,%1,%2,%3};"
        : "+f"(d[0]), "+f"(d[1]), "+f"(d[2]), "+f"(d[3])
        : "r"(a[0]), "r"(a[1]), "r"(a[2]), "r"(a[3]), "r"(b0), "r"(b1));
}
// hi/lo bf16 split of two floats packed into u32 (a = low half)
__device__ __forceinline__ uint32_t split2(float a, float b, uint32_t& lo) {
    __nv_bfloat16 ha = __float2bfloat16_rn(a), hb = __float2bfloat16_rn(b);
    float ra = a - __bfloat162float(ha), rb = b - __bfloat162float(hb);
    lo = (uint32_t)__bfloat16_as_ushort(__float2bfloat16_rn(ra)) |
         ((uint32_t)__bfloat16_as_ushort(__float2bfloat16_rn(rb)) << 16);
    return (uint32_t)__bfloat16_as_ushort(ha) |
           ((uint32_t)__bfloat16_as_ushort(hb) << 16);
}

// ---------------------------------------------------------------------------
// Prep: per-joint B tiles (w0 slice transposed to [k][n], bf16 hi/lo split)
// ---------------------------------------------------------------------------
__global__ void prep_b(const float* __restrict__ w0) {
    int idx = blockIdx.x * 256 + threadIdx.x;
    if (idx >= NJ * 48 * NH) return;
    int j = idx / (48 * NH), rem = idx % (48 * NH);
    int k = rem / NH, n = rem % NH;
    float v = (k < NI) ? w0[(j * NI + k) * NH + n] : 0.f;
    __nv_bfloat16 h = __float2bfloat16_rn(v);
    float r = v - __bfloat162float(h);
    int si = j * (48 * 72) + k * 72 + n;
    g_Bh[si] = __bfloat16_as_ushort(h);
    g_Bl[si] = __bfloat16_as_ushort(__float2bfloat16_rn(r));
}

// ---------------------------------------------------------------------------
// Kernel 1: per-128-pt tile: features -> bf16-split mma.sync GEMM -> layer2
// ---------------------------------------------------------------------------
__global__ __launch_bounds__(128)
void weights_mma(const float* __restrict__ xyz,
                 const float* __restrict__ transforms,
                 const float* __restrict__ w1)
{
    __shared__ __align__(16) char sm[SM_SZ];
    const uint32_t sb = smem_u32(sm);
    const int tid = threadIdx.x, lane = tid & 31, w = tid >> 5;
    const int n = blockIdx.x * 128 + tid;

    for (int i = tid; i < NJ * 16; i += 128)
        ((float*)(sm + SM_TR))[i] = transforms[i];
    // zero A pad chunk (cols 40..47 -> bytes 80..95) of every row, both splits
    {
        const uint4 zz = make_uint4(0, 0, 0, 0);
        *(uint4*)(sm + SM_AH + tid * 112 + 80) = zz;
        *(uint4*)(sm + SM_AL + tid * 112 + 80) = zz;
    }

    const float x = xyz[3 * n + 0];
    const float y = xyz[3 * n + 1];
    const float z = xyz[3 * n + 2];

    float acc[2][8][4];
#pragma unroll
    for (int a = 0; a < 2; ++a)
#pragma unroll
        for (int b = 0; b < 8; ++b)
#pragma unroll
            for (int c = 0; c < 4; ++c) acc[a][b][c] = 0.f;

    const int oct = lane >> 3, oi = lane & 7;

    for (int j = 0; j < NJ; ++j) {
        __syncthreads();   // prev iteration's ldmatrix complete (and init writes on j==0)

        // stage this joint's B tiles (432 uint4 each)
        {
            const uint4* sh = (const uint4*)(g_Bh + j * (48 * 72));
            const uint4* sl = (const uint4*)(g_Bl + j * (48 * 72));
            uint4* dh = (uint4*)(sm + SM_BH);
            uint4* dl = (uint4*)(sm + SM_BL);
            for (int i = tid; i < 432; i += 128) { dh[i] = sh[i]; dl[i] = sl[i]; }
        }

        // features for this thread's point
        float f[40];
        {
            const float* T = (const float*)(sm + SM_TR) + j * 16;
            float lx = fmaf(T[0], x, fmaf(T[1], y, fmaf(T[2],  z, T[3])));
            float ly = fmaf(T[4], x, fmaf(T[5], y, fmaf(T[6],  z, T[7])));
            float lz = fmaf(T[8], x, fmaf(T[9], y, fmaf(T[10], z, T[11])));
            const float INV = 2.0f / 3.0f;
            lx = (lx + 1.5f) * INV - 1.0f;
            ly = (ly + 1.5f) * INV - 1.0f;
            lz = (lz + 1.5f) * INV - 1.0f;
            f[0] = lx; f[1] = ly; f[2] = lz;
            float fx = lx, fy = ly, fz = lz;
#pragma unroll
            for (int ff = 0; ff < 6; ++ff) {
                float sx, cx, sy, cy, sz, cz;
                __sincosf(fx, &sx, &cx);
                __sincosf(fy, &sy, &cy);
                __sincosf(fz, &sz, &cz);
                f[3 + 6 * ff + 0] = sx; f[3 + 6 * ff + 1] = sy; f[3 + 6 * ff + 2] = sz;
                f[3 + 6 * ff + 3] = cx; f[3 + 6 * ff + 4] = cy; f[3 + 6 * ff + 5] = cz;
                fx += fx; fy += fy; fz += fz;
            }
            f[39] = 0.f;
        }
        // split + store A row (5 x 16B per split)
#pragma unroll
        for (int c = 0; c < 5; ++c) {
            uint4 H, L;
            H.x = split2(f[8 * c + 0], f[8 * c + 1], L.x);
            H.y = split2(f[8 * c + 2], f[8 * c + 3], L.y);
            H.z = split2(f[8 * c + 4], f[8 * c + 5], L.z);
            H.w = split2(f[8 * c + 6], f[8 * c + 7], L.w);
            *(uint4*)(sm + SM_AH + tid * 112 + c * 16) = H;
            *(uint4*)(sm + SM_AL + tid * 112 + c * 16) = L;
        }
        __syncthreads();

        // ldmatrix + mma: warp w computes rows [w*32, w*32+32) x all 64 cols
#pragma unroll
        for (int ks = 0; ks < 3; ++ks) {
            uint32_t ah[2][4], al[2][4];
#pragma unroll
            for (int mt = 0; mt < 2; ++mt) {
                uint32_t ra = (uint32_t)((w * 32 + mt * 16 + (oct & 1) * 8 + oi) * 112
                                         + ks * 32 + (oct >> 1) * 16);
                ldsm4(ah[mt], sb + SM_AH + ra);
                ldsm4(al[mt], sb + SM_AL + ra);
            }
#pragma unroll
            for (int np = 0; np < 4; ++np) {
                uint32_t rb = (uint32_t)((ks * 16 + (oct & 1) * 8 + oi) * 144
                                         + np * 32 + (oct >> 1) * 16);
                uint32_t bh[4], bl[4];
                ldsm4t(bh, sb + SM_BH + rb);
                ldsm4t(bl, sb + SM_BL + rb);
#pragma unroll
                for (int mt = 0; mt < 2; ++mt) {
                    mma16816(acc[mt][2 * np + 0], ah[mt], bh[0], bh[1]);
                    mma16816(acc[mt][2 * np + 0], ah[mt], bl[0], bl[1]);
                    mma16816(acc[mt][2 * np + 0], al[mt], bh[0], bh[1]);
                    mma16816(acc[mt][2 * np + 1], ah[mt], bh[2], bh[3]);
                    mma16816(acc[mt][2 * np + 1], ah[mt], bl[2], bl[3]);
                    mma16816(acc[mt][2 * np + 1], al[mt], bh[2], bh[3]);
                }
            }
        }
    }
    __syncthreads();   // all ldmatrix done; A/B regions can be reused

    // Epilogue: relu(acc) -> h smem [128 x 64] (row stride 65 f32)
    float* hs = (float*)(sm + SM_H);
#pragma unroll
    for (int mt = 0; mt < 2; ++mt) {
        const int rr = w * 32 + mt * 16 + (lane >> 2);
#pragma unroll
        for (int nt = 0; nt < 8; ++nt) {
            const int cc = nt * 8 + (lane & 3) * 2;
            hs[rr * 65 + cc]           = fmaxf(acc[mt][nt][0], 0.f);
            hs[rr * 65 + cc + 1]       = fmaxf(acc[mt][nt][1], 0.f);
            hs[(rr + 8) * 65 + cc]     = fmaxf(acc[mt][nt][2], 0.f);
            hs[(rr + 8) * 65 + cc + 1] = fmaxf(acc[mt][nt][3], 0.f);
        }
    }
    for (int i = tid; i < (NH * NJ) / 4; i += 128)
        ((float4*)(sm + SM_W1))[i] = ((const float4*)w1)[i];
    __syncthreads();

    // Layer 2 + relu, store row-major [N, NJ]
    const float* myrow = hs + tid * 65;
    float ra[NH];
#pragma unroll
    for (int k = 0; k < NH; ++k) ra[k] = myrow[k];

    const float* sw1 = (const float*)(sm + SM_W1);
    float* gout = &g_h[(size_t)n * NJ];
#pragma unroll 1
    for (int jj = 0; jj < NJ; ++jj) {
        float s = 0.f;
#pragma unroll
        for (int k = 0; k < NH; ++k) s = fmaf(ra[k], sw1[k * NJ + jj], s);
        gout[jj] = fmaxf(s, 0.f);
    }
}

// ---------------------------------------------------------------------------
// Kernel 2: scrambled-weight readback + normalized transform blend (unchanged)
// ---------------------------------------------------------------------------
__global__ __launch_bounds__(256)
void warp_kernel(const float* __restrict__ xyz,
                 const float* __restrict__ vdir,
                 const float* __restrict__ transforms,
                 float* __restrict__ out)
{
    __shared__ float str[NJ * 16];
    const int tid = threadIdx.x;
    const int m   = blockIdx.x * 256 + tid;
    for (int i = tid; i < NJ * 16; i += 256) str[i] = transforms[i];
    __syncthreads();

    float w[NJ];
    float s = 0.f;
#pragma unroll
    for (int j = 0; j < NJ; ++j) {
        w[j] = g_h[(size_t)j * NPTS + m];
        s += w[j];
    }
    const float inv = 1.0f / (s + 1e-6f);

    const float x  = xyz[3 * m + 0], y  = xyz[3 * m + 1], z  = xyz[3 * m + 2];
    const float vx = vdir[3 * m + 0], vy = vdir[3 * m + 1], vz = vdir[3 * m + 2];
    const float x2 = x - vx, y2 = y - vy, z2 = z - vz;

    float a1x = 0.f, a1y = 0.f, a1z = 0.f;
    float a2x = 0.f, a2y = 0.f, a2z = 0.f;
#pragma unroll
    for (int j = 0; j < NJ; ++j) {
        const float wn = w[j] * inv;
        const float* T = &str[j * 16];
        a1x = fmaf(wn, fmaf(T[0], x,  fmaf(T[1], y,  fmaf(T[2],  z,  T[3]))),  a1x);
        a1y = fmaf(wn, fmaf(T[4], x,  fmaf(T[5], y,  fmaf(T[6],  z,  T[7]))),  a1y);
        a1z = fmaf(wn, fmaf(T[8], x,  fmaf(T[9], y,  fmaf(T[10], z,  T[11]))), a1z);
        a2x = fmaf(wn, fmaf(T[0], x2, fmaf(T[1], y2, fmaf(T[2],  z2, T[3]))),  a2x);
        a2y = fmaf(wn, fmaf(T[4], x2, fmaf(T[5], y2, fmaf(T[6],  z2, T[7]))),  a2y);
        a2z = fmaf(wn, fmaf(T[8], x2, fmaf(T[9], y2, fmaf(T[10], z2, T[11]))), a2z);
    }

    out[3 * m + 0] = a1x;
    out[3 * m + 1] = a1y;
    out[3 * m + 2] = a1z;
    float* o2 = out + (size_t)3 * NPTS;
    o2[3 * m + 0] = a1x - a2x;
    o2[3 * m + 1] = a1y - a2y;
    o2[3 * m + 2] = a1z - a2z;
}

// ---------------------------------------------------------------------------
// Inputs: xyz_sampled, viewdirs, transforms, ray_valid(unused), w0, w1
// ---------------------------------------------------------------------------
extern "C" void kernel_launch(void* const* d_in, const int* in_sizes, int n_in,
                              void* d_out, int out_size)
{
    const float* xyz = (const float*)d_in[0];
    const float* vd  = (const float*)d_in[1];
    const float* tr  = (const float*)d_in[2];
    const float* w0  = (const float*)d_in[4];
    const float* w1  = (const float*)d_in[5];
    float* out = (float*)d_out;

    prep_b<<<(NJ * 48 * NH + 255) / 256, 256>>>(w0);
    weights_mma<<<NPTS / 128, 128>>>(xyz, tr, w1);
    warp_kernel<<<NPTS / 256, 256>>>(xyz, vd, tr, out);
}

// round 6
// speedup vs baseline: 2.5465x; 1.1860x over previous
#include <cuda_runtime.h>
#include <cuda_bf16.h>
#include <cstdint>
#include <math.h>

// Problem constants (R=1024, S=128, J=24, H=64, multires=6)
constexpr int NPTS = 1024 * 128;
constexpr int NJ   = 24;
constexpr int NH   = 64;
constexpr int NI   = 39;
constexpr int NPH  = 12;     // phases: 2 joints each
constexpr int KP   = 80;     // K per phase: 39 + 1 pad + 39 + 1 pad
constexpr int ASTR = 176;    // A row stride bytes (80 cols * 2B = 160, pad to 176)
constexpr int BSTR = 144;    // B row stride bytes (64 cols * 2B = 128, pad to 144)

// ---- dynamic SMEM layout ----
constexpr int SM_AH  = 0;                       // 128 x 176  = 22528
constexpr int SM_AL  = 22528;                   //             45056
constexpr int SM_B0H = 45056;                   // 80 x 144   = 11520
constexpr int SM_B0L = 56576;
constexpr int SM_B1H = 68096;
constexpr int SM_B1L = 79616;
constexpr int SM_TR  = 91136;                   // 24x16 f32  = 1536
constexpr int SM_SZ  = 92672;
// epilogue overlays: H[128 x 65 f32] at 0 (33280B), W1[64x24 f32] at SM_B0H

// relu(h) row-major [NPTS, NJ]; warp_kernel reads the faithful view(J,-1).T
// scramble as linear index j*NPTS + m.
__device__ float g_h[(size_t)NPTS * NJ];
// Pre-split B images per phase: [80 k][72 n-stride] bf16 (byte image of tile)
__device__ __align__(16) unsigned short g_Bh[NPH * KP * 72];
__device__ __align__(16) unsigned short g_Bl[NPH * KP * 72];

// ---------------- helpers ----------------
__device__ __forceinline__ uint32_t smem_u32(const void* p) {
    uint32_t a;
    asm("{ .reg .u64 t; cvta.to.shared.u64 t, %1; cvt.u32.u64 %0, t; }" : "=r"(a) : "l"(p));
    return a;
}
__device__ __forceinline__ void ldsm4(uint32_t* r, uint32_t addr) {
    asm volatile("ldmatrix.sync.aligned.m8n8.x4.shared.b16 {%0,%1,%2,%3}, [%4];"
                 : "=r"(r[0]), "=r"(r[1]), "=r"(r[2]), "=r"(r[3]) : "r"(addr));
}
__device__ __forceinline__ void ldsm4t(uint32_t* r, uint32_t addr) {
    asm volatile("ldmatrix.sync.aligned.m8n8.x4.trans.shared.b16 {%0,%1,%2,%3}, [%4];"
                 : "=r"(r[0]), "=r"(r[1]), "=r"(r[2]), "=r"(r[3]) : "r"(addr));
}
__device__ __forceinline__ void mma16816(float* d, const uint32_t* a,
                                         uint32_t b0, uint32_t b1) {
    asm volatile(
        "mma.sync.aligned.m16n8k16.row.col.f32.bf16.bf16.f32 "
        "{%0,%1,%2,%3}, {%4,%5,%6,%7}, {%8,%9}, {%0,%1,%2,%3};"
        : "+f"(d[0]), "+f"(d[1]), "+f"(d[2]), "+f"(d[3])
        : "r"(a[0]), "r"(a[1]), "r"(a[2]), "r"(a[3]), "r"(b0), "r"(b1));
}
// split two floats into packed bf16 hi + packed bf16 lo (a = low half)
__device__ __forceinline__ uint32_t split2(float a, float b, uint32_t& lo) {
    uint32_t h2;
    asm("cvt.rn.bf16x2.f32 %0, %1, %2;" : "=r"(h2) : "f"(b), "f"(a));
    float ahf = __uint_as_float(h2 << 16);
    float bhf = __uint_as_float(h2 & 0xFFFF0000u);
    float ra = a - ahf, rb = b - bhf;
    uint32_t l2;
    asm("cvt.rn.bf16x2.f32 %0, %1, %2;" : "=r"(l2) : "f"(rb), "f"(ra));
    lo = l2;
    return h2;
}

// ---------------------------------------------------------------------------
// Prep: per-phase B tiles: k rows 0..38 = joint 2p, 39 zero, 40..78 = joint
// 2p+1, 79 zero.  B[k][n] = w0[(j*39 + k)*64 + n], bf16 hi/lo split.
// ---------------------------------------------------------------------------
__global__ void prep_b(const float* __restrict__ w0) {
    int idx = blockIdx.x * 256 + threadIdx.x;
    if (idx >= NPH * KP * NH) return;
    int p = idx / (KP * NH), rem = idx % (KP * NH);
    int kk = rem / NH, n = rem % NH;
    float v = 0.f;
    if (kk < NI)                  v = w0[((2 * p)     * NI + kk)        * NH + n];
    else if (kk >= 40 && kk < 79) v = w0[((2 * p + 1) * NI + (kk - 40)) * NH + n];
    __nv_bfloat16 h = __float2bfloat16_rn(v);
    float r = v - __bfloat162float(h);
    int si = p * (KP * 72) + kk * 72 + n;
    g_Bh[si] = __bfloat16_as_ushort(h);
    g_Bl[si] = __bfloat16_as_ushort(__float2bfloat16_rn(r));
}

// ---------------------------------------------------------------------------
// Kernel 1: 128-pt tile; 12 phases of (stage B | features+split+A-store |
// sync | ldmatrix+mma x3 passes). A is warp-private => no A syncs.
// ---------------------------------------------------------------------------
__global__ __launch_bounds__(128)
void weights_mma(const float* __restrict__ xyz,
                 const float* __restrict__ transforms,
                 const float* __restrict__ w1)
{
    extern __shared__ __align__(16) char sm[];
    const uint32_t sb = smem_u32(sm);
    const int tid = threadIdx.x, lane = tid & 31, w = tid >> 5;
    const int n = blockIdx.x * 128 + tid;
    const int oct = lane >> 3, oi = lane & 7;

    for (int i = tid; i < NJ * 16; i += 128)
        ((float*)(sm + SM_TR))[i] = transforms[i];
    __syncthreads();

    const float x = xyz[3 * n + 0];
    const float y = xyz[3 * n + 1];
    const float z = xyz[3 * n + 2];

    float acc[2][8][4];
#pragma unroll
    for (int a = 0; a < 2; ++a)
#pragma unroll
        for (int b = 0; b < 8; ++b)
#pragma unroll
            for (int c = 0; c < 4; ++c) acc[a][b][c] = 0.f;

    for (int p = 0; p < NPH; ++p) {
        const int bH = (p & 1) ? SM_B1H : SM_B0H;
        const int bL = (p & 1) ? SM_B1L : SM_B0L;

        // stage this phase's B tiles (720 uint4 per split) — L2-resident
        {
            const uint4* shp = (const uint4*)(g_Bh + p * (KP * 72));
            const uint4* slp = (const uint4*)(g_Bl + p * (KP * 72));
            uint4* dh = (uint4*)(sm + bH);
            uint4* dl = (uint4*)(sm + bL);
            for (int i = tid; i < 720; i += 128) { dh[i] = shp[i]; dl[i] = slp[i]; }
        }

        // features + split + A-row store for both joints of this phase
        // (A rows are warp-private: own ldmatrix of phase p-1 already ordered)
#pragma unroll
        for (int half = 0; half < 2; ++half) {
            const int j = 2 * p + half;
            float f[40];
            {
                const float* T = (const float*)(sm + SM_TR) + j * 16;
                float lx = fmaf(T[0], x, fmaf(T[1], y, fmaf(T[2],  z, T[3])));
                float ly = fmaf(T[4], x, fmaf(T[5], y, fmaf(T[6],  z, T[7])));
                float lz = fmaf(T[8], x, fmaf(T[9], y, fmaf(T[10], z, T[11])));
                const float INV = 2.0f / 3.0f;
                lx = (lx + 1.5f) * INV - 1.0f;
                ly = (ly + 1.5f) * INV - 1.0f;
                lz = (lz + 1.5f) * INV - 1.0f;
                f[0] = lx; f[1] = ly; f[2] = lz;
                float fx = lx, fy = ly, fz = lz;
#pragma unroll
                for (int ff = 0; ff < 6; ++ff) {
                    float sx, cx, sy, cy, sz, cz;
                    __sincosf(fx, &sx, &cx);
                    __sincosf(fy, &sy, &cy);
                    __sincosf(fz, &sz, &cz);
                    f[3 + 6 * ff + 0] = sx; f[3 + 6 * ff + 1] = sy; f[3 + 6 * ff + 2] = sz;
                    f[3 + 6 * ff + 3] = cx; f[3 + 6 * ff + 4] = cy; f[3 + 6 * ff + 5] = cz;
                    fx += fx; fy += fy; fz += fz;
                }
                f[39] = 0.f;   // pad column inside the 16B chunk
            }
#pragma unroll
            for (int c = 0; c < 5; ++c) {
                uint4 H, L;
                H.x = split2(f[8 * c + 0], f[8 * c + 1], L.x);
                H.y = split2(f[8 * c + 2], f[8 * c + 3], L.y);
                H.z = split2(f[8 * c + 4], f[8 * c + 5], L.z);
                H.w = split2(f[8 * c + 6], f[8 * c + 7], L.w);
                const int off = tid * ASTR + half * 80 + c * 16;
                *(uint4*)(sm + SM_AH + off) = H;
                *(uint4*)(sm + SM_AL + off) = L;
            }
        }
        __syncthreads();   // B(buf) staged by all; also releases buf for p+2

        // ldmatrix + mma: warp w computes rows [w*32, w*32+32) x 64 cols
#pragma unroll
        for (int ks = 0; ks < 5; ++ks) {
            uint32_t ah[2][4], al[2][4];
#pragma unroll
            for (int mt = 0; mt < 2; ++mt) {
                uint32_t ra = (uint32_t)((w * 32 + mt * 16 + (oct & 1) * 8 + oi) * ASTR
                                         + ks * 32 + (oct >> 1) * 16);
                ldsm4(ah[mt], sb + SM_AH + ra);
                ldsm4(al[mt], sb + SM_AL + ra);
            }
#pragma unroll
            for (int np = 0; np < 4; ++np) {
                uint32_t rb = (uint32_t)((ks * 16 + (oct & 1) * 8 + oi) * BSTR
                                         + np * 32 + (oct >> 1) * 16);
                uint32_t bh[4], bl[4];
                ldsm4t(bh, sb + bH + rb);
                ldsm4t(bl, sb + bL + rb);
#pragma unroll
                for (int mt = 0; mt < 2; ++mt) {
                    mma16816(acc[mt][2 * np + 0], ah[mt], bh[0], bh[1]);
                    mma16816(acc[mt][2 * np + 0], ah[mt], bl[0], bl[1]);
                    mma16816(acc[mt][2 * np + 0], al[mt], bh[0], bh[1]);
                    mma16816(acc[mt][2 * np + 1], ah[mt], bh[2], bh[3]);
                    mma16816(acc[mt][2 * np + 1], ah[mt], bl[2], bl[3]);
                    mma16816(acc[mt][2 * np + 1], al[mt], bh[2], bh[3]);
                }
            }
        }
    }
    __syncthreads();   // all warps done with A/B regions

    // Epilogue: relu(acc) -> H smem [128 x 64], stride 65 f32 (overlays A)
    float* hs = (float*)(sm + 0);
#pragma unroll
    for (int mt = 0; mt < 2; ++mt) {
        const int rr = w * 32 + mt * 16 + (lane >> 2);
#pragma unroll
        for (int nt = 0; nt < 8; ++nt) {
            const int cc = nt * 8 + (lane & 3) * 2;
            hs[rr * 65 + cc]           = fmaxf(acc[mt][nt][0], 0.f);
            hs[rr * 65 + cc + 1]       = fmaxf(acc[mt][nt][1], 0.f);
            hs[(rr + 8) * 65 + cc]     = fmaxf(acc[mt][nt][2], 0.f);
            hs[(rr + 8) * 65 + cc + 1] = fmaxf(acc[mt][nt][3], 0.f);
        }
    }
    for (int i = tid; i < (NH * NJ) / 4; i += 128)
        ((float4*)(sm + SM_B0H))[i] = ((const float4*)w1)[i];
    __syncthreads();

    // Layer 2 + relu, store row-major [N, NJ]
    const float* myrow = hs + tid * 65;
    float ra[NH];
#pragma unroll
    for (int k = 0; k < NH; ++k) ra[k] = myrow[k];

    const float* sw1 = (const float*)(sm + SM_B0H);
    float* gout = &g_h[(size_t)n * NJ];
#pragma unroll 1
    for (int jj = 0; jj < NJ; ++jj) {
        float s = 0.f;
#pragma unroll
        for (int k = 0; k < NH; ++k) s = fmaf(ra[k], sw1[k * NJ + jj], s);
        gout[jj] = fmaxf(s, 0.f);
    }
}

// ---------------------------------------------------------------------------
// Kernel 2: scrambled-weight readback + normalized transform blend (unchanged)
// ---------------------------------------------------------------------------
__global__ __launch_bounds__(256)
void warp_kernel(const float* __restrict__ xyz,
                 const float* __restrict__ vdir,
                 const float* __restrict__ transforms,
                 float* __restrict__ out)
{
    __shared__ float str[NJ * 16];
    const int tid = threadIdx.x;
    const int m   = blockIdx.x * 256 + tid;
    for (int i = tid; i < NJ * 16; i += 256) str[i] = transforms[i];
    __syncthreads();

    float w[NJ];
    float s = 0.f;
#pragma unroll
    for (int j = 0; j < NJ; ++j) {
        w[j] = g_h[(size_t)j * NPTS + m];
        s += w[j];
    }
    const float inv = 1.0f / (s + 1e-6f);

    const float x  = xyz[3 * m + 0], y  = xyz[3 * m + 1], z  = xyz[3 * m + 2];
    const float vx = vdir[3 * m + 0], vy = vdir[3 * m + 1], vz = vdir[3 * m + 2];
    const float x2 = x - vx, y2 = y - vy, z2 = z - vz;

    float a1x = 0.f, a1y = 0.f, a1z = 0.f;
    float a2x = 0.f, a2y = 0.f, a2z = 0.f;
#pragma unroll
    for (int j = 0; j < NJ; ++j) {
        const float wn = w[j] * inv;
        const float* T = &str[j * 16];
        a1x = fmaf(wn, fmaf(T[0], x,  fmaf(T[1], y,  fmaf(T[2],  z,  T[3]))),  a1x);
        a1y = fmaf(wn, fmaf(T[4], x,  fmaf(T[5], y,  fmaf(T[6],  z,  T[7]))),  a1y);
        a1z = fmaf(wn, fmaf(T[8], x,  fmaf(T[9], y,  fmaf(T[10], z,  T[11]))), a1z);
        a2x = fmaf(wn, fmaf(T[0], x2, fmaf(T[1], y2, fmaf(T[2],  z2, T[3]))),  a2x);
        a2y = fmaf(wn, fmaf(T[4], y2, fmaf(T[5], y2, fmaf(T[6],  z2, T[7]))),  a2y);
        a2z = fmaf(wn, fmaf(T[8], x2, fmaf(T[9], y2, fmaf(T[10], z2, T[11]))), a2z);
    }
    // NOTE: a2y line above must use x2 — correct it explicitly:
    // (recomputed below to guarantee correctness)
    a2y = 0.f;
#pragma unroll
    for (int j = 0; j < NJ; ++j) {
        const float wn = w[j] * inv;
        const float* T = &str[j * 16];
        a2y = fmaf(wn, fmaf(T[4], x2, fmaf(T[5], y2, fmaf(T[6], z2, T[7]))), a2y);
    }

    out[3 * m + 0] = a1x;
    out[3 * m + 1] = a1y;
    out[3 * m + 2] = a1z;
    float* o2 = out + (size_t)3 * NPTS;
    o2[3 * m + 0] = a1x - a2x;
    o2[3 * m + 1] = a1y - a2y;
    o2[3 * m + 2] = a1z - a2z;
}

// ---------------------------------------------------------------------------
// Inputs: xyz_sampled, viewdirs, transforms, ray_valid(unused), w0, w1
// ---------------------------------------------------------------------------
extern "C" void kernel_launch(void* const* d_in, const int* in_sizes, int n_in,
                              void* d_out, int out_size)
{
    const float* xyz = (const float*)d_in[0];
    const float* vd  = (const float*)d_in[1];
    const float* tr  = (const float*)d_in[2];
    const float* w0  = (const float*)d_in[4];
    const float* w1  = (const float*)d_in[5];
    float* out = (float*)d_out;

    // Unconditional every call: deterministic, not a stream op (capture-safe),
    // no static guards (harness rule).
    cudaFuncSetAttribute(weights_mma, cudaFuncAttributeMaxDynamicSharedMemorySize, SM_SZ);

    prep_b<<<(NPH * KP * NH + 255) / 256, 256>>>(w0);
    weights_mma<<<NPTS / 128, 128, SM_SZ>>>(xyz, tr, w1);
    warp_kernel<<<NPTS / 256, 256>>>(xyz, vd, tr, out);
}

// round 7
// speedup vs baseline: 2.9542x; 1.1601x over previous
#include <cuda_runtime.h>
#include <cuda_bf16.h>
#include <cstdint>
#include <math.h>

// Problem constants (R=1024, S=128, J=24, H=64, multires=6)
constexpr int NPTS = 1024 * 128;
constexpr int NJ   = 24;
constexpr int NH   = 64;
constexpr int NI   = 39;
constexpr int NPH  = 12;     // phases: 2 joints each
constexpr int KP   = 80;     // K per phase: 39 + 1 pad + 39 + 1 pad
constexpr int ASTR = 176;    // A row stride bytes (80 cols * 2B = 160, pad to 176)
constexpr int BSTR = 144;    // B row stride bytes (64 cols * 2B = 128, pad to 144)

// ---- dynamic SMEM layout ----
constexpr int SM_AH  = 0;                       // 128 x 176  = 22528
constexpr int SM_AL  = 22528;                   //             45056
constexpr int SM_B0H = 45056;                   // 80 x 144   = 11520
constexpr int SM_B0L = 56576;
constexpr int SM_B1H = 68096;
constexpr int SM_B1L = 79616;
constexpr int SM_TR  = 91136;                   // 24x16 f32  = 1536
constexpr int SM_SZ  = 92672;
// epilogue overlays: H[128 x 65 f32] at 0 (33280B), W1[64x24 f32] at SM_B0H

// relu(h) row-major [NPTS, NJ]; warp_kernel reads the faithful view(J,-1).T
// scramble as linear index j*NPTS + m.
__device__ float g_h[(size_t)NPTS * NJ];
// Pre-split B images per phase: [80 k][72 n-stride] bf16 (byte image of tile)
__device__ __align__(16) unsigned short g_Bh[NPH * KP * 72];
__device__ __align__(16) unsigned short g_Bl[NPH * KP * 72];

// ---------------- helpers ----------------
__device__ __forceinline__ uint32_t smem_u32(const void* p) {
    uint32_t a;
    asm("{ .reg .u64 t; cvta.to.shared.u64 t, %1; cvt.u32.u64 %0, t; }" : "=r"(a) : "l"(p));
    return a;
}
__device__ __forceinline__ void ldsm4(uint32_t* r, uint32_t addr) {
    asm volatile("ldmatrix.sync.aligned.m8n8.x4.shared.b16 {%0,%1,%2,%3}, [%4];"
                 : "=r"(r[0]), "=r"(r[1]), "=r"(r[2]), "=r"(r[3]) : "r"(addr));
}
__device__ __forceinline__ void ldsm4t(uint32_t* r, uint32_t addr) {
    asm volatile("ldmatrix.sync.aligned.m8n8.x4.trans.shared.b16 {%0,%1,%2,%3}, [%4];"
                 : "=r"(r[0]), "=r"(r[1]), "=r"(r[2]), "=r"(r[3]) : "r"(addr));
}
__device__ __forceinline__ void mma16816(float* d, const uint32_t* a,
                                         uint32_t b0, uint32_t b1) {
    asm volatile(
        "mma.sync.aligned.m16n8k16.row.col.f32.bf16.bf16.f32 "
        "{%0,%1,%2,%3}, {%4,%5,%6,%7}, {%8,%9}, {%0,%1,%2,%3};"
        : "+f"(d[0]), "+f"(d[1]), "+f"(d[2]), "+f"(d[3])
        : "r"(a[0]), "r"(a[1]), "r"(a[2]), "r"(a[3]), "r"(b0), "r"(b1));
}
// split two floats into packed bf16 hi + packed bf16 lo (a = low half)
__device__ __forceinline__ uint32_t split2(float a, float b, uint32_t& lo) {
    uint32_t h2;
    asm("cvt.rn.bf16x2.f32 %0, %1, %2;" : "=r"(h2) : "f"(b), "f"(a));
    float ahf = __uint_as_float(h2 << 16);
    float bhf = __uint_as_float(h2 & 0xFFFF0000u);
    float ra = a - ahf, rb = b - bhf;
    uint32_t l2;
    asm("cvt.rn.bf16x2.f32 %0, %1, %2;" : "=r"(l2) : "f"(rb), "f"(ra));
    lo = l2;
    return h2;
}

// ---------------------------------------------------------------------------
// Prep: per-phase B tiles: k rows 0..38 = joint 2p, 39 zero, 40..78 = joint
// 2p+1, 79 zero.  B[k][n] = w0[(j*39 + k)*64 + n], bf16 hi/lo split.
// ---------------------------------------------------------------------------
__global__ void prep_b(const float* __restrict__ w0) {
    int idx = blockIdx.x * 256 + threadIdx.x;
    if (idx >= NPH * KP * NH) return;
    int p = idx / (KP * NH), rem = idx % (KP * NH);
    int kk = rem / NH, n = rem % NH;
    float v = 0.f;
    if (kk < NI)                  v = w0[((2 * p)     * NI + kk)        * NH + n];
    else if (kk >= 40 && kk < 79) v = w0[((2 * p + 1) * NI + (kk - 40)) * NH + n];
    __nv_bfloat16 h = __float2bfloat16_rn(v);
    float r = v - __bfloat162float(h);
    int si = p * (KP * 72) + kk * 72 + n;
    g_Bh[si] = __bfloat16_as_ushort(h);
    g_Bl[si] = __bfloat16_as_ushort(__float2bfloat16_rn(r));
}

// ---------------------------------------------------------------------------
// Kernel 1: 128-pt tile, 256 threads (8 warps).
// Feature work: thread (pt, half) computes joint 2p+half of point pt.
// GEMM: warp w => rows [(w&3)*32, +32), cols [(w>>2)*32, +32).
// ---------------------------------------------------------------------------
__global__ __launch_bounds__(256, 2)
void weights_mma(const float* __restrict__ xyz,
                 const float* __restrict__ transforms,
                 const float* __restrict__ w1)
{
    extern __shared__ __align__(16) char sm[];
    const uint32_t sb = smem_u32(sm);
    const int tid = threadIdx.x, lane = tid & 31, w = tid >> 5;
    const int pt = tid & 127, half = tid >> 7;
    const int wr = w & 3, wc = w >> 2;
    const int n = blockIdx.x * 128 + pt;
    const int oct = lane >> 3, oi = lane & 7;

    for (int i = tid; i < NJ * 16; i += 256)
        ((float*)(sm + SM_TR))[i] = transforms[i];
    __syncthreads();

    const float x = xyz[3 * n + 0];
    const float y = xyz[3 * n + 1];
    const float z = xyz[3 * n + 2];

    float acc[2][4][4];
#pragma unroll
    for (int a = 0; a < 2; ++a)
#pragma unroll
        for (int b = 0; b < 4; ++b)
#pragma unroll
            for (int c = 0; c < 4; ++c) acc[a][b][c] = 0.f;

    for (int p = 0; p < NPH; ++p) {
        const int bH = (p & 1) ? SM_B1H : SM_B0H;
        const int bL = (p & 1) ? SM_B1L : SM_B0L;

        // stage this phase's B tiles (double-buffered, safe before sync)
        {
            const uint4* shp = (const uint4*)(g_Bh + p * (KP * 72));
            const uint4* slp = (const uint4*)(g_Bl + p * (KP * 72));
            uint4* dh = (uint4*)(sm + bH);
            uint4* dl = (uint4*)(sm + bL);
            for (int i = tid; i < 720; i += 256) { dh[i] = shp[i]; dl[i] = slp[i]; }
        }

        // features for joint (2p + half) of point pt — registers only
        float f[40];
        {
            const int j = 2 * p + half;
            const float* T = (const float*)(sm + SM_TR) + j * 16;
            float lx = fmaf(T[0], x, fmaf(T[1], y, fmaf(T[2],  z, T[3])));
            float ly = fmaf(T[4], x, fmaf(T[5], y, fmaf(T[6],  z, T[7])));
            float lz = fmaf(T[8], x, fmaf(T[9], y, fmaf(T[10], z, T[11])));
            const float INV = 2.0f / 3.0f;
            lx = (lx + 1.5f) * INV - 1.0f;
            ly = (ly + 1.5f) * INV - 1.0f;
            lz = (lz + 1.5f) * INV - 1.0f;
            f[0] = lx; f[1] = ly; f[2] = lz;
            float fx = lx, fy = ly, fz = lz;
#pragma unroll
            for (int ff = 0; ff < 6; ++ff) {
                float sx, cx, sy, cy, sz, cz;
                __sincosf(fx, &sx, &cx);
                __sincosf(fy, &sy, &cy);
                __sincosf(fz, &sz, &cz);
                f[3 + 6 * ff + 0] = sx; f[3 + 6 * ff + 1] = sy; f[3 + 6 * ff + 2] = sz;
                f[3 + 6 * ff + 3] = cx; f[3 + 6 * ff + 4] = cy; f[3 + 6 * ff + 5] = cz;
                fx += fx; fy += fy; fz += fz;
            }
            f[39] = 0.f;   // pad column inside the 16B chunk
        }

        __syncthreads();   // all warps done reading A of phase p-1

        // split + store this thread's A half-row (5 x 16B per split)
#pragma unroll
        for (int c = 0; c < 5; ++c) {
            uint4 H, L;
            H.x = split2(f[8 * c + 0], f[8 * c + 1], L.x);
            H.y = split2(f[8 * c + 2], f[8 * c + 3], L.y);
            H.z = split2(f[8 * c + 4], f[8 * c + 5], L.z);
            H.w = split2(f[8 * c + 6], f[8 * c + 7], L.w);
            const int off = pt * ASTR + half * 80 + c * 16;
            *(uint4*)(sm + SM_AH + off) = H;
            *(uint4*)(sm + SM_AL + off) = L;
        }
        __syncthreads();   // A + B staged

        // ldmatrix + mma: warp computes rows [wr*32,+32) x cols [wc*32,+32)
#pragma unroll
        for (int ks = 0; ks < 5; ++ks) {
            uint32_t ah[2][4], al[2][4];
#pragma unroll
            for (int mt = 0; mt < 2; ++mt) {
                uint32_t ra = (uint32_t)((wr * 32 + mt * 16 + (oct & 1) * 8 + oi) * ASTR
                                         + ks * 32 + (oct >> 1) * 16);
                ldsm4(ah[mt], sb + SM_AH + ra);
                ldsm4(al[mt], sb + SM_AL + ra);
            }
#pragma unroll
            for (int np = 0; np < 2; ++np) {
                uint32_t rb = (uint32_t)((ks * 16 + (oct & 1) * 8 + oi) * BSTR
                                         + wc * 64 + np * 32 + (oct >> 1) * 16);
                uint32_t bh[4], bl[4];
                ldsm4t(bh, sb + bH + rb);
                ldsm4t(bl, sb + bL + rb);
#pragma unroll
                for (int mt = 0; mt < 2; ++mt) {
                    mma16816(acc[mt][2 * np + 0], ah[mt], bh[0], bh[1]);
                    mma16816(acc[mt][2 * np + 0], ah[mt], bl[0], bl[1]);
                    mma16816(acc[mt][2 * np + 0], al[mt], bh[0], bh[1]);
                    mma16816(acc[mt][2 * np + 1], ah[mt], bh[2], bh[3]);
                    mma16816(acc[mt][2 * np + 1], ah[mt], bl[2], bl[3]);
                    mma16816(acc[mt][2 * np + 1], al[mt], bh[2], bh[3]);
                }
            }
        }
    }
    __syncthreads();   // all warps done with A/B regions

    // Epilogue: relu(acc) -> H smem [128 x 64], stride 65 f32 (overlays A)
    float* hs = (float*)(sm + 0);
#pragma unroll
    for (int mt = 0; mt < 2; ++mt) {
        const int rr = wr * 32 + mt * 16 + (lane >> 2);
#pragma unroll
        for (int nt = 0; nt < 4; ++nt) {
            const int cc = wc * 32 + nt * 8 + (lane & 3) * 2;
            hs[rr * 65 + cc]           = fmaxf(acc[mt][nt][0], 0.f);
            hs[rr * 65 + cc + 1]       = fmaxf(acc[mt][nt][1], 0.f);
            hs[(rr + 8) * 65 + cc]     = fmaxf(acc[mt][nt][2], 0.f);
            hs[(rr + 8) * 65 + cc + 1] = fmaxf(acc[mt][nt][3], 0.f);
        }
    }
    for (int i = tid; i < (NH * NJ) / 4; i += 256)
        ((float4*)(sm + SM_B0H))[i] = ((const float4*)w1)[i];
    __syncthreads();

    // Layer 2 + relu: thread (pt, half) does row pt, jj in [half*12, half*12+12)
    const float* myrow = hs + pt * 65;
    float ra[NH];
#pragma unroll
    for (int k = 0; k < NH; ++k) ra[k] = myrow[k];

    const float* sw1 = (const float*)(sm + SM_B0H);
    float* gout = &g_h[(size_t)n * NJ];
    const int jj0 = half * 12;
#pragma unroll 1
    for (int jj = jj0; jj < jj0 + 12; ++jj) {
        float s = 0.f;
#pragma unroll
        for (int k = 0; k < NH; ++k) s = fmaf(ra[k], sw1[k * NJ + jj], s);
        gout[jj] = fmaxf(s, 0.f);
    }
}

// ---------------------------------------------------------------------------
// Kernel 2: scrambled-weight readback + normalized transform blend
// ---------------------------------------------------------------------------
__global__ __launch_bounds__(256)
void warp_kernel(const float* __restrict__ xyz,
                 const float* __restrict__ vdir,
                 const float* __restrict__ transforms,
                 float* __restrict__ out)
{
    __shared__ float str[NJ * 16];
    const int tid = threadIdx.x;
    const int m   = blockIdx.x * 256 + tid;
    for (int i = tid; i < NJ * 16; i += 256) str[i] = transforms[i];
    __syncthreads();

    float w[NJ];
    float s = 0.f;
#pragma unroll
    for (int j = 0; j < NJ; ++j) {
        w[j] = g_h[(size_t)j * NPTS + m];
        s += w[j];
    }
    const float inv = 1.0f / (s + 1e-6f);

    const float x  = xyz[3 * m + 0], y  = xyz[3 * m + 1], z  = xyz[3 * m + 2];
    const float vx = vdir[3 * m + 0], vy = vdir[3 * m + 1], vz = vdir[3 * m + 2];
    const float x2 = x - vx, y2 = y - vy, z2 = z - vz;

    float a1x = 0.f, a1y = 0.f, a1z = 0.f;
    float a2x = 0.f, a2y = 0.f, a2z = 0.f;
#pragma unroll
    for (int j = 0; j < NJ; ++j) {
        const float wn = w[j] * inv;
        const float* T = &str[j * 16];
        a1x = fmaf(wn, fmaf(T[0], x,  fmaf(T[1], y,  fmaf(T[2],  z,  T[3]))),  a1x);
        a1y = fmaf(wn, fmaf(T[4], x,  fmaf(T[5], y,  fmaf(T[6],  z,  T[7]))),  a1y);
        a1z = fmaf(wn, fmaf(T[8], x,  fmaf(T[9], y,  fmaf(T[10], z,  T[11]))), a1z);
        a2x = fmaf(wn, fmaf(T[0], x2, fmaf(T[1], y2, fmaf(T[2],  z2, T[3]))),  a2x);
        a2y = fmaf(wn, fmaf(T[4], x2, fmaf(T[5], y2, fmaf(T[6],  z2, T[7]))),  a2y);
        a2z = fmaf(wn, fmaf(T[8], x2, fmaf(T[9], y2, fmaf(T[10], z2, T[11]))), a2z);
    }

    out[3 * m + 0] = a1x;
    out[3 * m + 1] = a1y;
    out[3 * m + 2] = a1z;
    float* o2 = out + (size_t)3 * NPTS;
    o2[3 * m + 0] = a1x - a2x;
    o2[3 * m + 1] = a1y - a2y;
    o2[3 * m + 2] = a1z - a2z;
}

// ---------------------------------------------------------------------------
// Inputs: xyz_sampled, viewdirs, transforms, ray_valid(unused), w0, w1
// ---------------------------------------------------------------------------
extern "C" void kernel_launch(void* const* d_in, const int* in_sizes, int n_in,
                              void* d_out, int out_size)
{
    const float* xyz = (const float*)d_in[0];
    const float* vd  = (const float*)d_in[1];
    const float* tr  = (const float*)d_in[2];
    const float* w0  = (const float*)d_in[4];
    const float* w1  = (const float*)d_in[5];
    float* out = (float*)d_out;

    // Unconditional every call: deterministic, not a stream op (capture-safe).
    cudaFuncSetAttribute(weights_mma, cudaFuncAttributeMaxDynamicSharedMemorySize, SM_SZ);

    prep_b<<<(NPH * KP * NH + 255) / 256, 256>>>(w0);
    weights_mma<<<NPTS / 128, 256, SM_SZ>>>(xyz, tr, w1);
    warp_kernel<<<NPTS / 256, 256>>>(xyz, vd, tr, out);
}

// round 8
// speedup vs baseline: 3.1305x; 1.0597x over previous
#include <cuda_runtime.h>
#include <cuda_bf16.h>
#include <cstdint>
#include <math.h>

// Problem constants (R=1024, S=128, J=24, H=64, multires=6)
constexpr int NPTS = 1024 * 128;
constexpr int NJ   = 24;
constexpr int NH   = 64;
constexpr int NI   = 39;
constexpr int NPH  = 12;     // phases: 2 joints each
constexpr int KP   = 80;     // K per phase: 39 + 1 pad + 39 + 1 pad
constexpr int ASTR = 176;    // A row stride bytes (80 cols * 2B = 160, pad to 176)
constexpr int BSTR = 144;    // B row stride bytes (64 cols * 2B = 128, pad to 144)

// ---- dynamic SMEM layout ----
constexpr int SM_AH  = 0;                       // 128 x 176  = 22528
constexpr int SM_AL  = 22528;                   //             45056
constexpr int SM_B0H = 45056;                   // 80 x 144   = 11520
constexpr int SM_B0L = 56576;
constexpr int SM_B1H = 68096;
constexpr int SM_B1L = 79616;
constexpr int SM_TR  = 91136;                   // 24x16 f32  = 1536
constexpr int SM_SZ  = 92672;
// epilogue overlays: H[128 x 65 f32] at 0 (33280B), W1[64x24 f32] at SM_B0H

// relu(h) row-major [NPTS, NJ]; warp_kernel reads the faithful view(J,-1).T
// scramble as linear index j*NPTS + m.
__device__ float g_h[(size_t)NPTS * NJ];
// Pre-split B images per phase: [80 k][72 n-stride] bf16 (byte image of tile)
__device__ __align__(16) unsigned short g_Bh[NPH * KP * 72];
__device__ __align__(16) unsigned short g_Bl[NPH * KP * 72];

// ---------------- helpers ----------------
__device__ __forceinline__ uint32_t smem_u32(const void* p) {
    uint32_t a;
    asm("{ .reg .u64 t; cvta.to.shared.u64 t, %1; cvt.u32.u64 %0, t; }" : "=r"(a) : "l"(p));
    return a;
}
__device__ __forceinline__ void ldsm4(uint32_t* r, uint32_t addr) {
    asm volatile("ldmatrix.sync.aligned.m8n8.x4.shared.b16 {%0,%1,%2,%3}, [%4];"
                 : "=r"(r[0]), "=r"(r[1]), "=r"(r[2]), "=r"(r[3]) : "r"(addr));
}
__device__ __forceinline__ void ldsm4t(uint32_t* r, uint32_t addr) {
    asm volatile("ldmatrix.sync.aligned.m8n8.x4.trans.shared.b16 {%0,%1,%2,%3}, [%4];"
                 : "=r"(r[0]), "=r"(r[1]), "=r"(r[2]), "=r"(r[3]) : "r"(addr));
}
__device__ __forceinline__ void mma16816(float* d, const uint32_t* a,
                                         uint32_t b0, uint32_t b1) {
    asm volatile(
        "mma.sync.aligned.m16n8k16.row.col.f32.bf16.bf16.f32 "
        "{%0,%1,%2,%3}, {%4,%5,%6,%7}, {%8,%9}, {%0,%1,%2,%3};"
        : "+f"(d[0]), "+f"(d[1]), "+f"(d[2]), "+f"(d[3])
        : "r"(a[0]), "r"(a[1]), "r"(a[2]), "r"(a[3]), "r"(b0), "r"(b1));
}
// split two floats into packed bf16 hi + packed bf16 lo (a = low half)
__device__ __forceinline__ uint32_t split2(float a, float b, uint32_t& lo) {
    uint32_t h2;
    asm("cvt.rn.bf16x2.f32 %0, %1, %2;" : "=r"(h2) : "f"(b), "f"(a));
    float ahf = __uint_as_float(h2 << 16);
    float bhf = __uint_as_float(h2 & 0xFFFF0000u);
    float ra = a - ahf, rb = b - bhf;
    uint32_t l2;
    asm("cvt.rn.bf16x2.f32 %0, %1, %2;" : "=r"(l2) : "f"(rb), "f"(ra));
    lo = l2;
    return h2;
}

// ---------------------------------------------------------------------------
// Prep: per-phase B tiles: k rows 0..38 = joint 2p, 39 zero, 40..78 = joint
// 2p+1, 79 zero.  B[k][n] = w0[(j*39 + k)*64 + n], bf16 hi/lo split.
// ---------------------------------------------------------------------------
__global__ void prep_b(const float* __restrict__ w0) {
    int idx = blockIdx.x * 256 + threadIdx.x;
    if (idx >= NPH * KP * NH) return;
    int p = idx / (KP * NH), rem = idx % (KP * NH);
    int kk = rem / NH, n = rem % NH;
    float v = 0.f;
    if (kk < NI)                  v = w0[((2 * p)     * NI + kk)        * NH + n];
    else if (kk >= 40 && kk < 79) v = w0[((2 * p + 1) * NI + (kk - 40)) * NH + n];
    __nv_bfloat16 h = __float2bfloat16_rn(v);
    float r = v - __bfloat162float(h);
    int si = p * (KP * 72) + kk * 72 + n;
    g_Bh[si] = __bfloat16_as_ushort(h);
    g_Bl[si] = __bfloat16_as_ushort(__float2bfloat16_rn(r));
}

// ---------------------------------------------------------------------------
// Kernel 1: 128-pt tile, 256 threads (8 warps).
// Feature work: thread (pt, half) computes joint 2p+half of point pt,
// using 3 __sincosf + double-angle recurrence (exact power-of-2 freqs).
// GEMM: warp w => rows [(w&3)*32, +32), cols [(w>>2)*32, +32).
// ---------------------------------------------------------------------------
__global__ __launch_bounds__(256, 2)
void weights_mma(const float* __restrict__ xyz,
                 const float* __restrict__ transforms,
                 const float* __restrict__ w1)
{
    extern __shared__ __align__(16) char sm[];
    const uint32_t sb = smem_u32(sm);
    const int tid = threadIdx.x, lane = tid & 31, w = tid >> 5;
    const int pt = tid & 127, half = tid >> 7;
    const int wr = w & 3, wc = w >> 2;
    const int n = blockIdx.x * 128 + pt;
    const int oct = lane >> 3, oi = lane & 7;

    for (int i = tid; i < NJ * 16; i += 256)
        ((float*)(sm + SM_TR))[i] = transforms[i];
    __syncthreads();

    const float x = xyz[3 * n + 0];
    const float y = xyz[3 * n + 1];
    const float z = xyz[3 * n + 2];

    float acc[2][4][4];
#pragma unroll
    for (int a = 0; a < 2; ++a)
#pragma unroll
        for (int b = 0; b < 4; ++b)
#pragma unroll
            for (int c = 0; c < 4; ++c) acc[a][b][c] = 0.f;

    for (int p = 0; p < NPH; ++p) {
        const int bH = (p & 1) ? SM_B1H : SM_B0H;
        const int bL = (p & 1) ? SM_B1L : SM_B0L;

        // stage this phase's B tiles (double-buffered, safe before sync)
        {
            const uint4* shp = (const uint4*)(g_Bh + p * (KP * 72));
            const uint4* slp = (const uint4*)(g_Bl + p * (KP * 72));
            uint4* dh = (uint4*)(sm + bH);
            uint4* dl = (uint4*)(sm + bL);
            for (int i = tid; i < 720; i += 256) { dh[i] = shp[i]; dl[i] = slp[i]; }
        }

        // features for joint (2p + half) of point pt — registers only
        float f[40];
        {
            const int j = 2 * p + half;
            const float* T = (const float*)(sm + SM_TR) + j * 16;
            float lx = fmaf(T[0], x, fmaf(T[1], y, fmaf(T[2],  z, T[3])));
            float ly = fmaf(T[4], x, fmaf(T[5], y, fmaf(T[6],  z, T[7])));
            float lz = fmaf(T[8], x, fmaf(T[9], y, fmaf(T[10], z, T[11])));
            const float INV = 2.0f / 3.0f;
            lx = (lx + 1.5f) * INV - 1.0f;
            ly = (ly + 1.5f) * INV - 1.0f;
            lz = (lz + 1.5f) * INV - 1.0f;
            f[0] = lx; f[1] = ly; f[2] = lz;
            // f=0 via MUFU (small args => tight error), f=1..5 via double-angle
            float sx, cx, sy, cy, sz, cz;
            __sincosf(lx, &sx, &cx);
            __sincosf(ly, &sy, &cy);
            __sincosf(lz, &sz, &cz);
            f[3] = sx; f[4] = sy; f[5] = sz;
            f[6] = cx; f[7] = cy; f[8] = cz;
#pragma unroll
            for (int ff = 1; ff < 6; ++ff) {
                // sin(2a) = 2 s c ; cos(2a) = 1 - 2 s^2
                float nsx = 2.f * sx * cx, ncx = fmaf(-2.f * sx, sx, 1.f);
                float nsy = 2.f * sy * cy, ncy = fmaf(-2.f * sy, sy, 1.f);
                float nsz = 2.f * sz * cz, ncz = fmaf(-2.f * sz, sz, 1.f);
                sx = nsx; cx = ncx; sy = nsy; cy = ncy; sz = nsz; cz = ncz;
                f[3 + 6 * ff + 0] = sx; f[3 + 6 * ff + 1] = sy; f[3 + 6 * ff + 2] = sz;
                f[3 + 6 * ff + 3] = cx; f[3 + 6 * ff + 4] = cy; f[3 + 6 * ff + 5] = cz;
            }
            f[39] = 0.f;   // pad column inside the 16B chunk
        }

        __syncthreads();   // all warps done reading A of phase p-1

        // split + store this thread's A half-row (5 x 16B per split)
#pragma unroll
        for (int c = 0; c < 5; ++c) {
            uint4 H, L;
            H.x = split2(f[8 * c + 0], f[8 * c + 1], L.x);
            H.y = split2(f[8 * c + 2], f[8 * c + 3], L.y);
            H.z = split2(f[8 * c + 4], f[8 * c + 5], L.z);
            H.w = split2(f[8 * c + 6], f[8 * c + 7], L.w);
            const int off = pt * ASTR + half * 80 + c * 16;
            *(uint4*)(sm + SM_AH + off) = H;
            *(uint4*)(sm + SM_AL + off) = L;
        }
        __syncthreads();   // A + B staged

        // ldmatrix + mma: warp computes rows [wr*32,+32) x cols [wc*32,+32)
#pragma unroll
        for (int ks = 0; ks < 5; ++ks) {
            uint32_t ah[2][4], al[2][4];
#pragma unroll
            for (int mt = 0; mt < 2; ++mt) {
                uint32_t ra = (uint32_t)((wr * 32 + mt * 16 + (oct & 1) * 8 + oi) * ASTR
                                         + ks * 32 + (oct >> 1) * 16);
                ldsm4(ah[mt], sb + SM_AH + ra);
                ldsm4(al[mt], sb + SM_AL + ra);
            }
#pragma unroll
            for (int np = 0; np < 2; ++np) {
                uint32_t rb = (uint32_t)((ks * 16 + (oct & 1) * 8 + oi) * BSTR
                                         + wc * 64 + np * 32 + (oct >> 1) * 16);
                uint32_t bh[4], bl[4];
                ldsm4t(bh, sb + bH + rb);
                ldsm4t(bl, sb + bL + rb);
#pragma unroll
                for (int mt = 0; mt < 2; ++mt) {
                    mma16816(acc[mt][2 * np + 0], ah[mt], bh[0], bh[1]);
                    mma16816(acc[mt][2 * np + 0], ah[mt], bl[0], bl[1]);
                    mma16816(acc[mt][2 * np + 0], al[mt], bh[0], bh[1]);
                    mma16816(acc[mt][2 * np + 1], ah[mt], bh[2], bh[3]);
                    mma16816(acc[mt][2 * np + 1], ah[mt], bl[2], bl[3]);
                    mma16816(acc[mt][2 * np + 1], al[mt], bh[2], bh[3]);
                }
            }
        }
    }
    __syncthreads();   // all warps done with A/B regions

    // Epilogue: relu(acc) -> H smem [128 x 64], stride 65 f32 (overlays A)
    float* hs = (float*)(sm + 0);
#pragma unroll
    for (int mt = 0; mt < 2; ++mt) {
        const int rr = wr * 32 + mt * 16 + (lane >> 2);
#pragma unroll
        for (int nt = 0; nt < 4; ++nt) {
            const int cc = wc * 32 + nt * 8 + (lane & 3) * 2;
            hs[rr * 65 + cc]           = fmaxf(acc[mt][nt][0], 0.f);
            hs[rr * 65 + cc + 1]       = fmaxf(acc[mt][nt][1], 0.f);
            hs[(rr + 8) * 65 + cc]     = fmaxf(acc[mt][nt][2], 0.f);
            hs[(rr + 8) * 65 + cc + 1] = fmaxf(acc[mt][nt][3], 0.f);
        }
    }
    for (int i = tid; i < (NH * NJ) / 4; i += 256)
        ((float4*)(sm + SM_B0H))[i] = ((const float4*)w1)[i];
    __syncthreads();

    // Layer 2 + relu: thread (pt, half) does row pt, jj in [half*12, half*12+12)
    const float* myrow = hs + pt * 65;
    float ra[NH];
#pragma unroll
    for (int k = 0; k < NH; ++k) ra[k] = myrow[k];

    const float* sw1 = (const float*)(sm + SM_B0H);
    float* gout = &g_h[(size_t)n * NJ];
    const int jj0 = half * 12;
#pragma unroll 1
    for (int jj = jj0; jj < jj0 + 12; ++jj) {
        float s = 0.f;
#pragma unroll
        for (int k = 0; k < NH; ++k) s = fmaf(ra[k], sw1[k * NJ + jj], s);
        gout[jj] = fmaxf(s, 0.f);
    }
}

// ---------------------------------------------------------------------------
// Kernel 2: scrambled-weight readback + normalized transform blend
// ---------------------------------------------------------------------------
__global__ __launch_bounds__(256)
void warp_kernel(const float* __restrict__ xyz,
                 const float* __restrict__ vdir,
                 const float* __restrict__ transforms,
                 float* __restrict__ out)
{
    __shared__ float str[NJ * 16];
    const int tid = threadIdx.x;
    const int m   = blockIdx.x * 256 + tid;
    for (int i = tid; i < NJ * 16; i += 256) str[i] = transforms[i];
    __syncthreads();

    float w[NJ];
    float s = 0.f;
#pragma unroll
    for (int j = 0; j < NJ; ++j) {
        w[j] = g_h[(size_t)j * NPTS + m];
        s += w[j];
    }
    const float inv = 1.0f / (s + 1e-6f);

    const float x  = xyz[3 * m + 0], y  = xyz[3 * m + 1], z  = xyz[3 * m + 2];
    const float vx = vdir[3 * m + 0], vy = vdir[3 * m + 1], vz = vdir[3 * m + 2];
    const float x2 = x - vx, y2 = y - vy, z2 = z - vz;

    float a1x = 0.f, a1y = 0.f, a1z = 0.f;
    float a2x = 0.f, a2y = 0.f, a2z = 0.f;
#pragma unroll
    for (int j = 0; j < NJ; ++j) {
        const float wn = w[j] * inv;
        const float* T = &str[j * 16];
        a1x = fmaf(wn, fmaf(T[0], x,  fmaf(T[1], y,  fmaf(T[2],  z,  T[3]))),  a1x);
        a1y = fmaf(wn, fmaf(T[4], x,  fmaf(T[5], y,  fmaf(T[6],  z,  T[7]))),  a1y);
        a1z = fmaf(wn, fmaf(T[8], x,  fmaf(T[9], y,  fmaf(T[10], z,  T[11]))), a1z);
        a2x = fmaf(wn, fmaf(T[0], x2, fmaf(T[1], y2, fmaf(T[2],  z2, T[3]))),  a2x);
        a2y = fmaf(wn, fmaf(T[4], x2, fmaf(T[5], y2, fmaf(T[6],  z2, T[7]))),  a2y);
        a2z = fmaf(wn, fmaf(T[8], x2, fmaf(T[9], y2, fmaf(T[10], z2, T[11]))), a2z);
    }

    out[3 * m + 0] = a1x;
    out[3 * m + 1] = a1y;
    out[3 * m + 2] = a1z;
    float* o2 = out + (size_t)3 * NPTS;
    o2[3 * m + 0] = a1x - a2x;
    o2[3 * m + 1] = a1y - a2y;
    o2[3 * m + 2] = a1z - a2z;
}

// ---------------------------------------------------------------------------
// Inputs: xyz_sampled, viewdirs, transforms, ray_valid(unused), w0, w1
// ---------------------------------------------------------------------------
extern "C" void kernel_launch(void* const* d_in, const int* in_sizes, int n_in,
                              void* d_out, int out_size)
{
    const float* xyz = (const float*)d_in[0];
    const float* vd  = (const float*)d_in[1];
    const float* tr  = (const float*)d_in[2];
    const float* w0  = (const float*)d_in[4];
    const float* w1  = (const float*)d_in[5];
    float* out = (float*)d_out;

    // Unconditional every call: deterministic, not a stream op (capture-safe).
    cudaFuncSetAttribute(weights_mma, cudaFuncAttributeMaxDynamicSharedMemorySize, SM_SZ);

    prep_b<<<(NPH * KP * NH + 255) / 256, 256>>>(w0);
    weights_mma<<<NPTS / 128, 256, SM_SZ>>>(xyz, tr, w1);
    warp_kernel<<<NPTS / 256, 256>>>(xyz, vd, tr, out);
}

// round 9
// speedup vs baseline: 4.5208x; 1.4441x over previous
#include <cuda_runtime.h>
#include <cuda_fp16.h>
#include <cstdint>
#include <math.h>

// Problem constants (R=1024, S=128, J=24, H=64, multires=6)
constexpr int NPTS = 1024 * 128;
constexpr int NJ   = 24;
constexpr int NH   = 64;
constexpr int NI   = 39;
constexpr int NPH  = 12;     // phases: 2 joints each
constexpr int KP   = 80;     // K per phase: 39 + 1 pad + 39 + 1 pad
constexpr int ASTR = 176;    // A row stride bytes (80 cols * 2B = 160, pad to 176)
constexpr int BSTR = 144;    // B row stride bytes (64 cols * 2B = 128, pad to 144)

// ---- dynamic SMEM layout ----
constexpr int SM_A   = 0;                       // A fp16: 128 x 176 = 22528
constexpr int SM_B0H = 22528;                   // 80 x 144 = 11520
constexpr int SM_B0L = 34048;
constexpr int SM_B1H = 45568;
constexpr int SM_B1L = 57088;
constexpr int SM_TR  = 68608;                   // 24x16 f32 = 1536
constexpr int SM_SZ  = 70144;                   // 3 CTAs/SM => 205.5KB
// epilogue overlays: H[128 x 65 f32] at 0 (33280B), W1 at SM_B1H

// relu(h) row-major [NPTS, NJ]; warp_kernel reads the faithful view(J,-1).T
// scramble as linear index j*NPTS + m.
__device__ float g_h[(size_t)NPTS * NJ];
// Pre-split fp16 B images per phase: [80 k][72 n-stride] (byte image of tile)
__device__ __align__(16) unsigned short g_Bh[NPH * KP * 72];
__device__ __align__(16) unsigned short g_Bl[NPH * KP * 72];

// ---------------- helpers ----------------
__device__ __forceinline__ uint32_t smem_u32(const void* p) {
    uint32_t a;
    asm("{ .reg .u64 t; cvta.to.shared.u64 t, %1; cvt.u32.u64 %0, t; }" : "=r"(a) : "l"(p));
    return a;
}
__device__ __forceinline__ void ldsm4(uint32_t* r, uint32_t addr) {
    asm volatile("ldmatrix.sync.aligned.m8n8.x4.shared.b16 {%0,%1,%2,%3}, [%4];"
                 : "=r"(r[0]), "=r"(r[1]), "=r"(r[2]), "=r"(r[3]) : "r"(addr));
}
__device__ __forceinline__ void ldsm4t(uint32_t* r, uint32_t addr) {
    asm volatile("ldmatrix.sync.aligned.m8n8.x4.trans.shared.b16 {%0,%1,%2,%3}, [%4];"
                 : "=r"(r[0]), "=r"(r[1]), "=r"(r[2]), "=r"(r[3]) : "r"(addr));
}
__device__ __forceinline__ void mma16816h(float* d, const uint32_t* a,
                                          uint32_t b0, uint32_t b1) {
    asm volatile(
        "mma.sync.aligned.m16n8k16.row.col.f32.f16.f16.f32 "
        "{%0,%1,%2,%3}, {%4,%5,%6,%7}, {%8,%9}, {%0,%1,%2,%3};"
        : "+f"(d[0]), "+f"(d[1]), "+f"(d[2]), "+f"(d[3])
        : "r"(a[0]), "r"(a[1]), "r"(a[2]), "r"(a[3]), "r"(b0), "r"(b1));
}
// pack two f32 -> f16x2 (a in low half)
__device__ __forceinline__ uint32_t packh2(float a, float b) {
    uint32_t r;
    asm("cvt.rn.f16x2.f32 %0, %1, %2;" : "=r"(r) : "f"(b), "f"(a));
    return r;
}

// ---------------------------------------------------------------------------
// Prep: per-phase B tiles: k rows 0..38 = joint 2p, 39 zero, 40..78 = joint
// 2p+1, 79 zero.  B[k][n] = w0[(j*39+k)*64 + n], fp16 hi/lo split (lo may be
// denormal — its own rounding contributes ~1e-6, negligible).
// ---------------------------------------------------------------------------
__global__ void prep_b(const float* __restrict__ w0) {
    int idx = blockIdx.x * 256 + threadIdx.x;
    if (idx >= NPH * KP * NH) return;
    int p = idx / (KP * NH), rem = idx % (KP * NH);
    int kk = rem / NH, n = rem % NH;
    float v = 0.f;
    if (kk < NI)                  v = w0[((2 * p)     * NI + kk)        * NH + n];
    else if (kk >= 40 && kk < 79) v = w0[((2 * p + 1) * NI + (kk - 40)) * NH + n];
    __half h = __float2half_rn(v);
    float r = v - __half2float(h);
    __half l = __float2half_rn(r);
    int si = p * (KP * 72) + kk * 72 + n;
    g_Bh[si] = __half_as_ushort(h);
    g_Bl[si] = __half_as_ushort(l);
}

// ---------------------------------------------------------------------------
// Kernel 1: 128-pt tile, 256 threads (8 warps), 3 CTAs/SM.
// Feature work: thread (pt, half) computes joint 2p+half of point pt,
// packed to fp16 pairs on the fly (carry-pair scheme, regs stay low).
// GEMM: 2-pass fp16: D = Ah*(Bh + Bl).  Warp w: rows (w&3)*32, cols (w>>2)*32.
// ---------------------------------------------------------------------------
__global__ __launch_bounds__(256, 3)
void weights_mma(const float* __restrict__ xyz,
                 const float* __restrict__ transforms,
                 const float* __restrict__ w1)
{
    extern __shared__ __align__(16) char sm[];
    const uint32_t sb = smem_u32(sm);
    const int tid = threadIdx.x, lane = tid & 31, w = tid >> 5;
    const int pt = tid & 127, half = tid >> 7;
    const int wr = w & 3, wc = w >> 2;
    const int n = blockIdx.x * 128 + pt;
    const int oct = lane >> 3, oi = lane & 7;

    for (int i = tid; i < NJ * 16; i += 256)
        ((float*)(sm + SM_TR))[i] = transforms[i];
    __syncthreads();

    const float x = xyz[3 * n + 0];
    const float y = xyz[3 * n + 1];
    const float z = xyz[3 * n + 2];

    float acc[2][4][4];
#pragma unroll
    for (int a = 0; a < 2; ++a)
#pragma unroll
        for (int b = 0; b < 4; ++b)
#pragma unroll
            for (int c = 0; c < 4; ++c) acc[a][b][c] = 0.f;

    for (int p = 0; p < NPH; ++p) {
        const int bH = (p & 1) ? SM_B1H : SM_B0H;
        const int bL = (p & 1) ? SM_B1L : SM_B0L;

        // stage this phase's B tiles (double-buffered, safe before sync)
        {
            const uint4* shp = (const uint4*)(g_Bh + p * (KP * 72));
            const uint4* slp = (const uint4*)(g_Bl + p * (KP * 72));
            uint4* dh = (uint4*)(sm + bH);
            uint4* dl = (uint4*)(sm + bL);
            for (int i = tid; i < 720; i += 256) { dh[i] = shp[i]; dl[i] = slp[i]; }
        }

        // features for joint (2p + half), packed to fp16 pairs on the fly
        uint32_t fp[20];
        {
            const int j = 2 * p + half;
            const float* T = (const float*)(sm + SM_TR) + j * 16;
            float lx = fmaf(T[0], x, fmaf(T[1], y, fmaf(T[2],  z, T[3])));
            float ly = fmaf(T[4], x, fmaf(T[5], y, fmaf(T[6],  z, T[7])));
            float lz = fmaf(T[8], x, fmaf(T[9], y, fmaf(T[10], z, T[11])));
            const float INV = 2.0f / 3.0f;
            lx = (lx + 1.5f) * INV - 1.0f;
            ly = (ly + 1.5f) * INV - 1.0f;
            lz = (lz + 1.5f) * INV - 1.0f;
            fp[0] = packh2(lx, ly);
            float carry = lz;                       // index 2, awaits sx0
            float sx, cx, sy, cy, sz, cz;
            __sincosf(lx, &sx, &cx);
            __sincosf(ly, &sy, &cy);
            __sincosf(lz, &sz, &cz);
#pragma unroll
            for (int ff = 0; ff < 6; ++ff) {
                fp[1 + 3 * ff] = packh2(carry, sx);
                fp[2 + 3 * ff] = packh2(sy, sz);
                fp[3 + 3 * ff] = packh2(cx, cy);
                carry = cz;
                if (ff < 5) {
                    // sin(2a) = 2 s c ; cos(2a) = 1 - 2 s^2
                    float nsx = 2.f * sx * cx, ncx = fmaf(-2.f * sx, sx, 1.f);
                    float nsy = 2.f * sy * cy, ncy = fmaf(-2.f * sy, sy, 1.f);
                    float nsz = 2.f * sz * cz, ncz = fmaf(-2.f * sz, sz, 1.f);
                    sx = nsx; cx = ncx; sy = nsy; cy = ncy; sz = nsz; cz = ncz;
                }
            }
            fp[19] = packh2(carry, 0.f);            // cz5 + pad column
        }

        __syncthreads();   // all warps done reading A of phase p-1

        // store this thread's fp16 A half-row (5 x 16B)
#pragma unroll
        for (int c = 0; c < 5; ++c) {
            uint4 H = make_uint4(fp[4 * c + 0], fp[4 * c + 1],
                                 fp[4 * c + 2], fp[4 * c + 3]);
            *(uint4*)(sm + SM_A + pt * ASTR + half * 80 + c * 16) = H;
        }
        __syncthreads();   // A + B staged

        // ldmatrix + mma: warp computes rows [wr*32,+32) x cols [wc*32,+32)
#pragma unroll
        for (int ks = 0; ks < 5; ++ks) {
            uint32_t ah[2][4];
#pragma unroll
            for (int mt = 0; mt < 2; ++mt) {
                uint32_t ra = (uint32_t)((wr * 32 + mt * 16 + (oct & 1) * 8 + oi) * ASTR
                                         + ks * 32 + (oct >> 1) * 16);
                ldsm4(ah[mt], sb + SM_A + ra);
            }
#pragma unroll
            for (int np = 0; np < 2; ++np) {
                uint32_t rb = (uint32_t)((ks * 16 + (oct & 1) * 8 + oi) * BSTR
                                         + wc * 64 + np * 32 + (oct >> 1) * 16);
                uint32_t bh[4], bl[4];
                ldsm4t(bh, sb + bH + rb);
                ldsm4t(bl, sb + bL + rb);
#pragma unroll
                for (int mt = 0; mt < 2; ++mt) {
                    mma16816h(acc[mt][2 * np + 0], ah[mt], bh[0], bh[1]);
                    mma16816h(acc[mt][2 * np + 0], ah[mt], bl[0], bl[1]);
                    mma16816h(acc[mt][2 * np + 1], ah[mt], bh[2], bh[3]);
                    mma16816h(acc[mt][2 * np + 1], ah[mt], bl[2], bl[3]);
                }
            }
        }
    }
    __syncthreads();   // all warps done with A/B regions

    // Epilogue: relu(acc) -> H smem [128 x 64], stride 65 f32 (overlays A/B0)
    float* hs = (float*)(sm + 0);
#pragma unroll
    for (int mt = 0; mt < 2; ++mt) {
        const int rr = wr * 32 + mt * 16 + (lane >> 2);
#pragma unroll
        for (int nt = 0; nt < 4; ++nt) {
            const int cc = wc * 32 + nt * 8 + (lane & 3) * 2;
            hs[rr * 65 + cc]           = fmaxf(acc[mt][nt][0], 0.f);
            hs[rr * 65 + cc + 1]       = fmaxf(acc[mt][nt][1], 0.f);
            hs[(rr + 8) * 65 + cc]     = fmaxf(acc[mt][nt][2], 0.f);
            hs[(rr + 8) * 65 + cc + 1] = fmaxf(acc[mt][nt][3], 0.f);
        }
    }
    for (int i = tid; i < (NH * NJ) / 4; i += 256)
        ((float4*)(sm + SM_B1H))[i] = ((const float4*)w1)[i];
    __syncthreads();

    // Layer 2 + relu: thread (pt, half) does row pt, jj in [half*12, half*12+12)
    const float* myrow = hs + pt * 65;
    float ra[NH];
#pragma unroll
    for (int k = 0; k < NH; ++k) ra[k] = myrow[k];

    const float* sw1 = (const float*)(sm + SM_B1H);
    float* gout = &g_h[(size_t)n * NJ];
    const int jj0 = half * 12;
#pragma unroll 1
    for (int jj = jj0; jj < jj0 + 12; ++jj) {
        float s = 0.f;
#pragma unroll
        for (int k = 0; k < NH; ++k) s = fmaf(ra[k], sw1[k * NJ + jj], s);
        gout[jj] = fmaxf(s, 0.f);
    }
}

// ---------------------------------------------------------------------------
// Kernel 2: scrambled-weight readback + normalized transform blend
// ---------------------------------------------------------------------------
__global__ __launch_bounds__(256)
void warp_kernel(const float* __restrict__ xyz,
                 const float* __restrict__ vdir,
                 const float* __restrict__ transforms,
                 float* __restrict__ out)
{
    __shared__ float str[NJ * 16];
    const int tid = threadIdx.x;
    const int m   = blockIdx.x * 256 + tid;
    for (int i = tid; i < NJ * 16; i += 256) str[i] = transforms[i];
    __syncthreads();

    float w[NJ];
    float s = 0.f;
#pragma unroll
    for (int j = 0; j < NJ; ++j) {
        w[j] = g_h[(size_t)j * NPTS + m];
        s += w[j];
    }
    const float inv = 1.0f / (s + 1e-6f);

    const float x  = xyz[3 * m + 0], y  = xyz[3 * m + 1], z  = xyz[3 * m + 2];
    const float vx = vdir[3 * m + 0], vy = vdir[3 * m + 1], vz = vdir[3 * m + 2];
    const float x2 = x - vx, y2 = y - vy, z2 = z - vz;

    float a1x = 0.f, a1y = 0.f, a1z = 0.f;
    float a2x = 0.f, a2y = 0.f, a2z = 0.f;
#pragma unroll
    for (int j = 0; j < NJ; ++j) {
        const float wn = w[j] * inv;
        const float* T = &str[j * 16];
        a1x = fmaf(wn, fmaf(T[0], x,  fmaf(T[1], y,  fmaf(T[2],  z,  T[3]))),  a1x);
        a1y = fmaf(wn, fmaf(T[4], x,  fmaf(T[5], y,  fmaf(T[6],  z,  T[7]))),  a1y);
        a1z = fmaf(wn, fmaf(T[8], x,  fmaf(T[9], y,  fmaf(T[10], z,  T[11]))), a1z);
        a2x = fmaf(wn, fmaf(T[0], x2, fmaf(T[1], y2, fmaf(T[2],  z2, T[3]))),  a2x);
        a2y = fmaf(wn, fmaf(T[4], x2, fmaf(T[5], y2, fmaf(T[6],  z2, T[7]))),  a2y);
        a2z = fmaf(wn, fmaf(T[8], x2, fmaf(T[9], y2, fmaf(T[10], z2, T[11]))), a2z);
    }

    out[3 * m + 0] = a1x;
    out[3 * m + 1] = a1y;
    out[3 * m + 2] = a1z;
    float* o2 = out + (size_t)3 * NPTS;
    o2[3 * m + 0] = a1x - a2x;
    o2[3 * m + 1] = a1y - a2y;
    o2[3 * m + 2] = a1z - a2z;
}

// ---------------------------------------------------------------------------
// Inputs: xyz_sampled, viewdirs, transforms, ray_valid(unused), w0, w1
// ---------------------------------------------------------------------------
extern "C" void kernel_launch(void* const* d_in, const int* in_sizes, int n_in,
                              void* d_out, int out_size)
{
    const float* xyz = (const float*)d_in[0];
    const float* vd  = (const float*)d_in[1];
    const float* tr  = (const float*)d_in[2];
    const float* w0  = (const float*)d_in[4];
    const float* w1  = (const float*)d_in[5];
    float* out = (float*)d_out;

    // Unconditional every call: deterministic, not a stream op (capture-safe).
    cudaFuncSetAttribute(weights_mma, cudaFuncAttributeMaxDynamicSharedMemorySize, SM_SZ);

    prep_b<<<(NPH * KP * NH + 255) / 256, 256>>>(w0);
    weights_mma<<<NPTS / 128, 256, SM_SZ>>>(xyz, tr, w1);
    warp_kernel<<<NPTS / 256, 256>>>(xyz, vd, tr, out);
}

// round 11
// speedup vs baseline: 5.6297x; 1.2453x over previous
#include <cuda_runtime.h>
#include <cuda_fp16.h>
#include <cstdint>
#include <math.h>

// Problem constants (R=1024, S=128, J=24, H=64, multires=6)
constexpr int NPTS = 1024 * 128;
constexpr int NJ   = 24;
constexpr int NH   = 64;
constexpr int NI   = 39;
constexpr int NPH  = 12;     // phases: 2 joints each
constexpr int KP   = 80;     // K per phase: 39 + 1 pad + 39 + 1 pad
constexpr int ASTR = 176;    // A row stride bytes (80 cols * 2B = 160, pad to 176)
constexpr int BSTR = 144;    // B row stride bytes (64 cols * 2B = 128, pad to 144)

// ---- dynamic SMEM layout ----
constexpr int SM_A   = 0;                       // A fp16: 128 x 176 = 22528
constexpr int SM_B0  = 22528;                   // 80 x 144 = 11520
constexpr int SM_B1  = 34048;
constexpr int SM_TR  = 45568;                   // 24x16 f32 = 1536
constexpr int SM_SZ  = 47104;
// epilogue overlays: H[128 x 65 f32] at 0 (33280B <= 34048), W1 at SM_B1

// relu(h) row-major [NPTS, NJ]; warp_kernel reads the faithful view(J,-1).T
// scramble as linear index j*NPTS + m.
__device__ float g_h[(size_t)NPTS * NJ];
// fp16 B images per phase: [80 k][72 n-stride] (byte image of the smem tile)
__device__ __align__(16) unsigned short g_Bh[NPH * KP * 72];

// ---------------- helpers ----------------
__device__ __forceinline__ uint32_t smem_u32(const void* p) {
    uint32_t a;
    asm("{ .reg .u64 t; cvta.to.shared.u64 t, %1; cvt.u32.u64 %0, t; }" : "=r"(a) : "l"(p));
    return a;
}
__device__ __forceinline__ void ldsm4(uint32_t* r, uint32_t addr) {
    asm volatile("ldmatrix.sync.aligned.m8n8.x4.shared.b16 {%0,%1,%2,%3}, [%4];"
                 : "=r"(r[0]), "=r"(r[1]), "=r"(r[2]), "=r"(r[3]) : "r"(addr));
}
__device__ __forceinline__ void ldsm4t(uint32_t* r, uint32_t addr) {
    asm volatile("ldmatrix.sync.aligned.m8n8.x4.trans.shared.b16 {%0,%1,%2,%3}, [%4];"
                 : "=r"(r[0]), "=r"(r[1]), "=r"(r[2]), "=r"(r[3]) : "r"(addr));
}
__device__ __forceinline__ void mma16816h(float* d, const uint32_t* a,
                                          uint32_t b0, uint32_t b1) {
    asm volatile(
        "mma.sync.aligned.m16n8k16.row.col.f32.f16.f16.f32 "
        "{%0,%1,%2,%3}, {%4,%5,%6,%7}, {%8,%9}, {%0,%1,%2,%3};"
        : "+f"(d[0]), "+f"(d[1]), "+f"(d[2]), "+f"(d[3])
        : "r"(a[0]), "r"(a[1]), "r"(a[2]), "r"(a[3]), "r"(b0), "r"(b1));
}
// pack two f32 -> f16x2 (a in low half)
__device__ __forceinline__ uint32_t packh2(float a, float b) {
    uint32_t r;
    asm("cvt.rn.f16x2.f32 %0, %1, %2;" : "=r"(r) : "f"(b), "f"(a));
    return r;
}

// ---------------------------------------------------------------------------
// Prep: per-phase B tiles: k rows 0..38 = joint 2p, 39 zero, 40..78 = joint
// 2p+1, 79 zero.  B[k][n] = fp16(w0[(j*39+k)*64 + n]).  Pad cols n=64..71
// are also zeroed so the whole 720-uint4 tile image is defined.
// ---------------------------------------------------------------------------
__global__ void prep_b(const float* __restrict__ w0) {
    int idx = blockIdx.x * 256 + threadIdx.x;
    if (idx >= NPH * KP * 72) return;
    int p = idx / (KP * 72), rem = idx % (KP * 72);
    int kk = rem / 72, n = rem % 72;
    float v = 0.f;
    if (n < NH) {
        if (kk < NI)                  v = w0[((2 * p)     * NI + kk)        * NH + n];
        else if (kk >= 40 && kk < 79) v = w0[((2 * p + 1) * NI + (kk - 40)) * NH + n];
    }
    g_Bh[p * (KP * 72) + kk * 72 + n] = __half_as_ushort(__float2half_rn(v));
}

// ---------------------------------------------------------------------------
// Kernel 1: 128-pt tile, 256 threads (8 warps).
// Feature work: thread (pt, half) computes joint 2p+half of point pt,
// packed to fp16 pairs on the fly. GEMM: single-pass fp16 D = Ah*Bh.
// Warp w: rows (w&3)*32, cols (w>>2)*32.
// ---------------------------------------------------------------------------
__global__ __launch_bounds__(256, 3)
void weights_mma(const float* __restrict__ xyz,
                 const float* __restrict__ transforms,
                 const float* __restrict__ w1)
{
    extern __shared__ __align__(16) char sm[];
    const uint32_t sb = smem_u32(sm);
    const int tid = threadIdx.x, lane = tid & 31, w = tid >> 5;
    const int pt = tid & 127, half = tid >> 7;
    const int wr = w & 3, wc = w >> 2;
    const int n = blockIdx.x * 128 + pt;
    const int oct = lane >> 3, oi = lane & 7;

    for (int i = tid; i < NJ * 16; i += 256)
        ((float*)(sm + SM_TR))[i] = transforms[i];
    __syncthreads();

    const float x = xyz[3 * n + 0];
    const float y = xyz[3 * n + 1];
    const float z = xyz[3 * n + 2];

    float acc[2][4][4];
#pragma unroll
    for (int a = 0; a < 2; ++a)
#pragma unroll
        for (int b = 0; b < 4; ++b)
#pragma unroll
            for (int c = 0; c < 4; ++c) acc[a][b][c] = 0.f;

    for (int p = 0; p < NPH; ++p) {
        const int bB = (p & 1) ? SM_B1 : SM_B0;

        // stage this phase's B tile: 80 rows x 144B = 720 uint4 (FULL tile)
        {
            const uint4* shp = (const uint4*)(g_Bh + p * (KP * 72));
            uint4* dh = (uint4*)(sm + bB);
            for (int i = tid; i < 720; i += 256) dh[i] = shp[i];
        }

        // features for joint (2p + half), packed to fp16 pairs on the fly
        uint32_t fp[20];
        {
            const int j = 2 * p + half;
            const float* T = (const float*)(sm + SM_TR) + j * 16;
            float lx = fmaf(T[0], x, fmaf(T[1], y, fmaf(T[2],  z, T[3])));
            float ly = fmaf(T[4], x, fmaf(T[5], y, fmaf(T[6],  z, T[7])));
            float lz = fmaf(T[8], x, fmaf(T[9], y, fmaf(T[10], z, T[11])));
            const float INV = 2.0f / 3.0f;
            lx = (lx + 1.5f) * INV - 1.0f;
            ly = (ly + 1.5f) * INV - 1.0f;
            lz = (lz + 1.5f) * INV - 1.0f;
            fp[0] = packh2(lx, ly);
            float carry = lz;                       // index 2, awaits sx0
            float sx, cx, sy, cy, sz, cz;
            __sincosf(lx, &sx, &cx);
            __sincosf(ly, &sy, &cy);
            __sincosf(lz, &sz, &cz);
#pragma unroll
            for (int ff = 0; ff < 6; ++ff) {
                fp[1 + 3 * ff] = packh2(carry, sx);
                fp[2 + 3 * ff] = packh2(sy, sz);
                fp[3 + 3 * ff] = packh2(cx, cy);
                carry = cz;
                if (ff < 5) {
                    // sin(2a) = 2 s c ; cos(2a) = 1 - 2 s^2
                    float nsx = 2.f * sx * cx, ncx = fmaf(-2.f * sx, sx, 1.f);
                    float nsy = 2.f * sy * cy, ncy = fmaf(-2.f * sy, sy, 1.f);
                    float nsz = 2.f * sz * cz, ncz = fmaf(-2.f * sz, sz, 1.f);
                    sx = nsx; cx = ncx; sy = nsy; cy = ncy; sz = nsz; cz = ncz;
                }
            }
            fp[19] = packh2(carry, 0.f);            // cz5 + pad column
        }

        __syncthreads();   // all warps done reading A of phase p-1

        // store this thread's fp16 A half-row (5 x 16B)
#pragma unroll
        for (int c = 0; c < 5; ++c) {
            uint4 H = make_uint4(fp[4 * c + 0], fp[4 * c + 1],
                                 fp[4 * c + 2], fp[4 * c + 3]);
            *(uint4*)(sm + SM_A + pt * ASTR + half * 80 + c * 16) = H;
        }
        __syncthreads();   // A + B staged

        // ldmatrix + mma: warp computes rows [wr*32,+32) x cols [wc*32,+32)
#pragma unroll
        for (int ks = 0; ks < 5; ++ks) {
            uint32_t ah[2][4];
#pragma unroll
            for (int mt = 0; mt < 2; ++mt) {
                uint32_t ra = (uint32_t)((wr * 32 + mt * 16 + (oct & 1) * 8 + oi) * ASTR
                                         + ks * 32 + (oct >> 1) * 16);
                ldsm4(ah[mt], sb + SM_A + ra);
            }
#pragma unroll
            for (int np = 0; np < 2; ++np) {
                uint32_t rb = (uint32_t)((ks * 16 + (oct & 1) * 8 + oi) * BSTR
                                         + wc * 64 + np * 32 + (oct >> 1) * 16);
                uint32_t bh[4];
                ldsm4t(bh, sb + bB + rb);
#pragma unroll
                for (int mt = 0; mt < 2; ++mt) {
                    mma16816h(acc[mt][2 * np + 0], ah[mt], bh[0], bh[1]);
                    mma16816h(acc[mt][2 * np + 1], ah[mt], bh[2], bh[3]);
                }
            }
        }
    }
    __syncthreads();   // all warps done with A/B regions

    // Epilogue: relu(acc) -> H smem [128 x 64], stride 65 f32 (overlays A/B0)
    float* hs = (float*)(sm + 0);
#pragma unroll
    for (int mt = 0; mt < 2; ++mt) {
        const int rr = wr * 32 + mt * 16 + (lane >> 2);
#pragma unroll
        for (int nt = 0; nt < 4; ++nt) {
            const int cc = wc * 32 + nt * 8 + (lane & 3) * 2;
            hs[rr * 65 + cc]           = fmaxf(acc[mt][nt][0], 0.f);
            hs[rr * 65 + cc + 1]       = fmaxf(acc[mt][nt][1], 0.f);
            hs[(rr + 8) * 65 + cc]     = fmaxf(acc[mt][nt][2], 0.f);
            hs[(rr + 8) * 65 + cc + 1] = fmaxf(acc[mt][nt][3], 0.f);
        }
    }
    for (int i = tid; i < (NH * NJ) / 4; i += 256)
        ((float4*)(sm + SM_B1))[i] = ((const float4*)w1)[i];
    __syncthreads();

    // Layer 2 + relu: thread (pt, half) does row pt, jj in [half*12, half*12+12)
    const float* myrow = hs + pt * 65;
    float ra[NH];
#pragma unroll
    for (int k = 0; k < NH; ++k) ra[k] = myrow[k];

    const float* sw1 = (const float*)(sm + SM_B1);
    float* gout = &g_h[(size_t)n * NJ];
    const int jj0 = half * 12;
#pragma unroll 1
    for (int jj = jj0; jj < jj0 + 12; ++jj) {
        float s = 0.f;
#pragma unroll
        for (int k = 0; k < NH; ++k) s = fmaf(ra[k], sw1[k * NJ + jj], s);
        gout[jj] = fmaxf(s, 0.f);
    }
}

// ---------------------------------------------------------------------------
// Kernel 2: scrambled-weight readback + normalized transform blend
// ---------------------------------------------------------------------------
__global__ __launch_bounds__(256)
void warp_kernel(const float* __restrict__ xyz,
                 const float* __restrict__ vdir,
                 const float* __restrict__ transforms,
                 float* __restrict__ out)
{
    __shared__ float str[NJ * 16];
    const int tid = threadIdx.x;
    const int m   = blockIdx.x * 256 + tid;
    for (int i = tid; i < NJ * 16; i += 256) str[i] = transforms[i];
    __syncthreads();

    float w[NJ];
    float s = 0.f;
#pragma unroll
    for (int j = 0; j < NJ; ++j) {
        w[j] = g_h[(size_t)j * NPTS + m];
        s += w[j];
    }
    const float inv = 1.0f / (s + 1e-6f);

    const float x  = xyz[3 * m + 0], y  = xyz[3 * m + 1], z  = xyz[3 * m + 2];
    const float vx = vdir[3 * m + 0], vy = vdir[3 * m + 1], vz = vdir[3 * m + 2];
    const float x2 = x - vx, y2 = y - vy, z2 = z - vz;

    float a1x = 0.f, a1y = 0.f, a1z = 0.f;
    float a2x = 0.f, a2y = 0.f, a2z = 0.f;
#pragma unroll
    for (int j = 0; j < NJ; ++j) {
        const float wn = w[j] * inv;
        const float* T = &str[j * 16];
        a1x = fmaf(wn, fmaf(T[0], x,  fmaf(T[1], y,  fmaf(T[2],  z,  T[3]))),  a1x);
        a1y = fmaf(wn, fmaf(T[4], x,  fmaf(T[5], y,  fmaf(T[6],  z,  T[7]))),  a1y);
        a1z = fmaf(wn, fmaf(T[8], x,  fmaf(T[9], y,  fmaf(T[10], z,  T[11]))), a1z);
        a2x = fmaf(wn, fmaf(T[0], x2, fmaf(T[1], y2, fmaf(T[2],  z2, T[3]))),  a2x);
        a2y = fmaf(wn, fmaf(T[4], x2, fmaf(T[5], y2, fmaf(T[6],  z2, T[7]))),  a2y);
        a2z = fmaf(wn, fmaf(T[8], x2, fmaf(T[9], y2, fmaf(T[10], z2, T[11]))), a2z);
    }

    out[3 * m + 0] = a1x;
    out[3 * m + 1] = a1y;
    out[3 * m + 2] = a1z;
    float* o2 = out + (size_t)3 * NPTS;
    o2[3 * m + 0] = a1x - a2x;
    o2[3 * m + 1] = a1y - a2y;
    o2[3 * m + 2] = a1z - a2z;
}

// ---------------------------------------------------------------------------
// Inputs: xyz_sampled, viewdirs, transforms, ray_valid(unused), w0, w1
// ---------------------------------------------------------------------------
extern "C" void kernel_launch(void* const* d_in, const int* in_sizes, int n_in,
                              void* d_out, int out_size)
{
    const float* xyz = (const float*)d_in[0];
    const float* vd  = (const float*)d_in[1];
    const float* tr  = (const float*)d_in[2];
    const float* w0  = (const float*)d_in[4];
    const float* w1  = (const float*)d_in[5];
    float* out = (float*)d_out;

    // Unconditional every call: deterministic, not a stream op (capture-safe).
    cudaFuncSetAttribute(weights_mma, cudaFuncAttributeMaxDynamicSharedMemorySize, SM_SZ);

    prep_b<<<(NPH * KP * 72 + 255) / 256, 256>>>(w0);
    weights_mma<<<NPTS / 128, 256, SM_SZ>>>(xyz, tr, w1);
    warp_kernel<<<NPTS / 256, 256>>>(xyz, vd, tr, out);
}